// round 1
// baseline (speedup 1.0000x reference)
#include <cuda_runtime.h>
#include <cuda_bf16.h>
#include <cstdint>

// Problem constants
#define NNODES 50000
#define NREL   8
#define NEDGES 100000
#define INF    128     // in features
#define OUTF   128     // out features
#define KDIM   (NREL * INF)   // 1024

// ---------------------------------------------------------------------------
// Device scratch (no runtime allocation allowed)
// ---------------------------------------------------------------------------
__device__ int   g_off [NREL * (NNODES + 1)];   // CSR offsets per relation (also histogram)
__device__ int   g_cur [NREL * NNODES];         // fill cursors
__device__ int   g_eidx[NREL * NEDGES];         // edge ids sorted by dst (per relation)
__device__ float g_agg [(size_t)NNODES * KDIM]; // [n][r*128+i]  204.8 MB

// ---------------------------------------------------------------------------
// 1) zero histogram + cursors
// ---------------------------------------------------------------------------
__global__ void zero_kernel() {
    int i = blockIdx.x * blockDim.x + threadIdx.x;
    if (i < NREL * (NNODES + 1)) g_off[i] = 0;
    if (i < NREL * NNODES)       g_cur[i] = 0;
}

// ---------------------------------------------------------------------------
// 2) histogram of dst per relation (counts land at off[r][d+1])
// ---------------------------------------------------------------------------
__global__ void hist_kernel(const int* __restrict__ dst) {
    int tid = blockIdx.x * blockDim.x + threadIdx.x;
    if (tid >= NREL * NEDGES) return;
    int r = tid / NEDGES;
    int d = dst[tid];
    atomicAdd(&g_off[r * (NNODES + 1) + d + 1], 1);
}

// ---------------------------------------------------------------------------
// 3) per-relation inclusive scan -> CSR offsets. 8 blocks, 1024 threads.
// ---------------------------------------------------------------------------
__global__ void scan_kernel() {
    int rel = blockIdx.x;
    int* off = g_off + rel * (NNODES + 1);
    __shared__ int wsum[32];
    __shared__ int carry_s;
    int tid = threadIdx.x, lane = tid & 31, wid = tid >> 5;
    if (tid == 0) carry_s = 0;
    __syncthreads();
    for (int chunk = 0; chunk < NNODES; chunk += 1024) {
        int i = chunk + tid;
        int v = (i < NNODES) ? off[1 + i] : 0;
        int x = v;
        #pragma unroll
        for (int o = 1; o < 32; o <<= 1) {
            int y = __shfl_up_sync(0xffffffffu, x, o);
            if (lane >= o) x += y;
        }
        if (lane == 31) wsum[wid] = x;
        __syncthreads();
        if (wid == 0) {
            int w = wsum[lane];
            #pragma unroll
            for (int o = 1; o < 32; o <<= 1) {
                int y = __shfl_up_sync(0xffffffffu, w, o);
                if (lane >= o) w += y;
            }
            wsum[lane] = w;
        }
        __syncthreads();
        int carry = carry_s;
        int add   = (wid > 0) ? wsum[wid - 1] : 0;
        int incl  = x + add + carry;
        if (i < NNODES) off[1 + i] = incl;
        __syncthreads();
        if (tid == 1023) carry_s = incl;   // chunk total + old carry
        __syncthreads();
    }
}

// ---------------------------------------------------------------------------
// 4) fill edge index lists (CSR by dst)
// ---------------------------------------------------------------------------
__global__ void fill_kernel(const int* __restrict__ dst) {
    int tid = blockIdx.x * blockDim.x + threadIdx.x;
    if (tid >= NREL * NEDGES) return;
    int r = tid / NEDGES;
    int e = tid - r * NEDGES;
    int d = dst[tid];
    int p = atomicAdd(&g_cur[r * NNODES + d], 1);
    int pos = g_off[r * (NNODES + 1) + d] + p;
    g_eidx[r * NEDGES + pos] = e;
}

// ---------------------------------------------------------------------------
// 5) aggregation: one warp per (node, relation), no float atomics.
//    agg[n][r*128 + i] = sum_{e: dst=n} vals[r][e] * inp[src[r][e]][i]
// ---------------------------------------------------------------------------
__global__ void agg_kernel(const float* __restrict__ inp,
                           const int*   __restrict__ src,
                           const float* __restrict__ vals) {
    int gw   = blockIdx.x * 8 + (threadIdx.x >> 5);   // global warp id, < 400000
    int lane = threadIdx.x & 31;
    int n = gw >> 3;
    int r = gw & 7;
    const int* off = g_off + r * (NNODES + 1);
    int s0 = off[n], s1 = off[n + 1];
    float4 acc = make_float4(0.f, 0.f, 0.f, 0.f);
    const float4* inp4 = (const float4*)inp;
    const int*   ei = g_eidx + r * NEDGES;
    const int*   sr = src    + r * NEDGES;
    const float* vl = vals   + r * NEDGES;
    for (int j = s0; j < s1; j++) {
        int   e = ei[j];
        float v = vl[e];
        int   s = sr[e];
        float4 xv = inp4[s * 32 + lane];
        acc.x += v * xv.x; acc.y += v * xv.y;
        acc.z += v * xv.z; acc.w += v * xv.w;
    }
    ((float4*)g_agg)[(size_t)n * 256 + r * 32 + lane] = acc;
}

// ---------------------------------------------------------------------------
// 6) GEMM: out[50000 x 128] = g_agg[50000 x 1024] @ W[1024 x 128]
//    fp32 with packed f32x2 FFMA (fma.rn.f32x2 -> FFMA2, 2x fma-pipe tput)
//    BM=128, BN=128, BK=16, 256 threads, 8x8 per thread.
// ---------------------------------------------------------------------------
__global__ void __launch_bounds__(256)
gemm_kernel(const float* __restrict__ W, float* __restrict__ out) {
    __shared__ __align__(16) float As[16][128];
    __shared__ __align__(16) float Bs[16][128];
    int tid = threadIdx.x;
    int m0  = blockIdx.x * 128;
    int tx  = tid & 15;          // 16 col-groups of 8
    int ty  = tid >> 4;          // 16 row-groups of 8

    unsigned long long acc[8][4];
    #pragma unroll
    for (int i = 0; i < 8; i++)
        #pragma unroll
        for (int j = 0; j < 4; j++) acc[i][j] = 0ull;   // {0.f, 0.f}

    for (int k0 = 0; k0 < KDIM; k0 += 16) {
        // load A tile (transpose into As[k][m]); guard M edge
        #pragma unroll
        for (int i = 0; i < 2; i++) {
            int s  = tid + 256 * i;      // 512 float4 slots
            int m  = s >> 2;
            int kq = s & 3;
            int row = m0 + m;
            float4 v = make_float4(0.f, 0.f, 0.f, 0.f);
            if (row < NNODES)
                v = *(const float4*)&g_agg[(size_t)row * KDIM + k0 + kq * 4];
            As[kq * 4 + 0][m] = v.x;
            As[kq * 4 + 1][m] = v.y;
            As[kq * 4 + 2][m] = v.z;
            As[kq * 4 + 3][m] = v.w;
        }
        // load B tile (weights are [1024][128] row-major already)
        #pragma unroll
        for (int i = 0; i < 2; i++) {
            int s  = tid + 256 * i;
            int k  = s >> 5;
            int nq = s & 31;
            *(float4*)&Bs[k][nq * 4] =
                *(const float4*)&W[(k0 + k) * 128 + nq * 4];
        }
        __syncthreads();
        #pragma unroll
        for (int kk = 0; kk < 16; kk++) {
            float4 a0 = *(const float4*)&As[kk][ty * 8];
            float4 a1 = *(const float4*)&As[kk][ty * 8 + 4];
            unsigned long long bb[4];
            const unsigned long long* bp =
                (const unsigned long long*)&Bs[kk][tx * 8];
            bb[0] = bp[0]; bb[1] = bp[1]; bb[2] = bp[2]; bb[3] = bp[3];
            float av[8] = {a0.x, a0.y, a0.z, a0.w, a1.x, a1.y, a1.z, a1.w};
            #pragma unroll
            for (int i = 0; i < 8; i++) {
                unsigned long long a2;
                asm("mov.b64 %0, {%1, %1};" : "=l"(a2) : "f"(av[i]));
                #pragma unroll
                for (int j = 0; j < 4; j++) {
                    asm("fma.rn.f32x2 %0, %1, %2, %0;"
                        : "+l"(acc[i][j]) : "l"(a2), "l"(bb[j]));
                }
            }
        }
        __syncthreads();
    }
    // epilogue: each acc pair is two consecutive output columns (little endian)
    #pragma unroll
    for (int i = 0; i < 8; i++) {
        int row = m0 + ty * 8 + i;
        if (row < NNODES) {
            unsigned long long* op =
                (unsigned long long*)&out[row * 128 + tx * 8];
            op[0] = acc[i][0]; op[1] = acc[i][1];
            op[2] = acc[i][2]; op[3] = acc[i][3];
        }
    }
}

// ---------------------------------------------------------------------------
// launch
// ---------------------------------------------------------------------------
extern "C" void kernel_launch(void* const* d_in, const int* in_sizes, int n_in,
                              void* d_out, int out_size) {
    const float* inp  = (const float*)d_in[0];
    const int*   src  = (const int*)  d_in[1];
    const int*   dst  = (const int*)  d_in[2];
    const float* vals = (const float*)d_in[3];
    const float* W    = (const float*)d_in[4];
    float* out = (float*)d_out;

    const int RE = NREL * NEDGES;                 // 800000
    const int ZN = NREL * (NNODES + 1);           // 400008

    zero_kernel<<<(ZN + 255) / 256, 256>>>();
    hist_kernel<<<(RE + 255) / 256, 256>>>(dst);
    scan_kernel<<<NREL, 1024>>>();
    fill_kernel<<<(RE + 255) / 256, 256>>>(dst);
    agg_kernel <<<NNODES, 256>>>(inp, src, vals);

    int mtiles = (NNODES + 127) / 128;            // 391
    gemm_kernel<<<mtiles, 256>>>(W, out);
}

// round 3
// speedup vs baseline: 1.9010x; 1.9010x over previous
#include <cuda_runtime.h>
#include <cstdint>

#define NNODES 50000
#define NREL   8
#define NEDGES 100000
#define NIDX   (NREL * NNODES)          // 400000
#define RE     (NREL * NEDGES)          // 800000
#define INPSZ  (NNODES * 128)           // 6.4M

// ---------------------------------------------------------------------------
// Device scratch (no runtime allocation allowed)
// ---------------------------------------------------------------------------
__device__ float g_inp_tf[(size_t)INPSZ];          // inp rounded to tf32
__device__ float g_Wtf[NREL * 128 * 128];          // W tf32-rounded, [r][k][n]
__device__ float g_H[2][(size_t)NNODES * 128];     // H_r = inp @ W_r (2 live)
__device__ int   g_cnt[NIDX];
__device__ int   g_cur[NIDX];
__device__ int   g_off[NIDX + 1];
__device__ int   g_bsum[128];
__device__ int   g_bbase[128];
__device__ int   g_esrc[RE];
__device__ float g_eval[RE];

__device__ __forceinline__ float to_tf32(float x) {
    uint32_t u;
    asm("cvt.rn.tf32.f32 %0, %1;" : "=r"(u) : "f"(x));
    return __uint_as_float(u);
}

// ---------------------------------------------------------------------------
// Prep (merged): zero counters, round inp + W to tf32
// ---------------------------------------------------------------------------
__global__ void k_prep(const float* __restrict__ inp, const float* __restrict__ W) {
    int i = blockIdx.x * 256 + threadIdx.x;
    if (i < INPSZ)            g_inp_tf[i] = to_tf32(inp[i]);
    if (i < NIDX)             { g_cnt[i] = 0; g_cur[i] = 0; }
    if (i < NREL * 128 * 128) g_Wtf[i] = to_tf32(W[i]);
}

__global__ void k_hist(const int* __restrict__ dst) {
    int tid = blockIdx.x * 256 + threadIdx.x;
    if (tid >= RE) return;
    int r = tid / NEDGES;
    atomicAdd(&g_cnt[r * NNODES + dst[tid]], 1);
}

__device__ __forceinline__ int wscan(int x, int lane) {
    #pragma unroll
    for (int o = 1; o < 32; o <<= 1) {
        int y = __shfl_up_sync(0xffffffffu, x, o);
        if (lane >= o) x += y;
    }
    return x;
}
__global__ void k_scanA() {
    __shared__ int ws[32];
    int t = threadIdx.x, lane = t & 31, wid = t >> 5;
    int base = blockIdx.x * 4096 + t * 4;
    int v[4];
    #pragma unroll
    for (int i = 0; i < 4; i++) v[i] = (base + i < NIDX) ? g_cnt[base + i] : 0;
    v[1] += v[0]; v[2] += v[1]; v[3] += v[2];
    int x = wscan(v[3], lane);
    if (lane == 31) ws[wid] = x;
    __syncthreads();
    if (wid == 0) ws[lane] = wscan(ws[lane], lane);
    __syncthreads();
    int pre = (wid ? ws[wid - 1] : 0) + (x - v[3]);
    #pragma unroll
    for (int i = 0; i < 4; i++)
        if (base + i < NIDX) g_off[base + i + 1] = pre + v[i];
    if (t == 1023) g_bsum[blockIdx.x] = ws[31];
}
__global__ void k_scanB(int nblk) {
    __shared__ int ws[4];
    int t = threadIdx.x, lane = t & 31, wid = t >> 5;
    int v = (t < nblk) ? g_bsum[t] : 0;
    int x = wscan(v, lane);
    if (lane == 31) ws[wid] = x;
    __syncthreads();
    if (t == 0) { int a = 0; for (int i = 0; i < 4; i++) { int tmp = ws[i]; ws[i] = a; a += tmp; } }
    __syncthreads();
    int incl = x + ws[wid];
    if (t < nblk) g_bbase[t] = incl - v;
}
__global__ void k_scanC() {
    int t = threadIdx.x;
    int add = g_bbase[blockIdx.x];
    int base = blockIdx.x * 4096 + t * 4;
    #pragma unroll
    for (int i = 0; i < 4; i++)
        if (base + i < NIDX) g_off[base + i + 1] += add;
    if (blockIdx.x == 0 && t == 0) g_off[0] = 0;
}
__global__ void k_fill(const int* __restrict__ dst, const int* __restrict__ src,
                       const float* __restrict__ vals) {
    int tid = blockIdx.x * 256 + threadIdx.x;
    if (tid >= RE) return;
    int r = tid / NEDGES;
    int idx = r * NNODES + dst[tid];
    int p = atomicAdd(&g_cur[idx], 1);
    int pos = g_off[idx] + p;
    g_esrc[pos] = src[tid];
    g_eval[pos] = vals[tid];
}

// ---------------------------------------------------------------------------
// GEMM: H[rr] = inp_tf @ W_r  via mma.sync m16n8k8 tf32
// CTA: 256 thr = 8 warps (2M x 4N). CTA tile 128x128, warp tile 64x32, BK=32.
// ---------------------------------------------------------------------------
#define AST 36    // As row stride (floats): banks 4g+t distinct
#define BST 136   // Bs row stride (floats): banks 8k+g distinct

__global__ void __launch_bounds__(256) k_gemm(int g) {
    __shared__ __align__(16) float As[128 * AST];   // [m][k] 18.4KB
    __shared__ __align__(16) float Bs[32 * BST];    // [k][n] 17.4KB

    int tid = threadIdx.x;
    int lane = tid & 31, wid = tid >> 5;
    int grp = lane >> 2, tg = lane & 3;            // groupID, threadInGroup
    int wm = wid & 1, wn = wid >> 1;               // warp M(2) x N(4)
    int m0 = blockIdx.x * 128;
    int r  = g * 2 + blockIdx.y;

    const float* A = g_inp_tf;
    const float* B = g_Wtf + r * 16384;

    float c[4][4][4];                               // [mi][nj][frag]
    #pragma unroll
    for (int i = 0; i < 4; i++)
        #pragma unroll
        for (int j = 0; j < 4; j++)
            c[i][j][0] = c[i][j][1] = c[i][j][2] = c[i][j][3] = 0.f;

    for (int kb = 0; kb < 128; kb += 32) {
        // load A tile 128x32 (row-major, stride AST)
        #pragma unroll
        for (int it = 0; it < 4; it++) {
            int s = it * 256 + tid;                 // 1024 float4 slots
            int m = s >> 3, kq = s & 7;
            int grow = m0 + m;
            float4 v = make_float4(0.f, 0.f, 0.f, 0.f);
            if (grow < NNODES)
                v = *(const float4*)&A[(size_t)grow * 128 + kb + kq * 4];
            *(float4*)&As[m * AST + kq * 4] = v;
        }
        // load B tile 32x128 (row-major, stride BST)
        #pragma unroll
        for (int it = 0; it < 4; it++) {
            int s = it * 256 + tid;
            int k = s >> 5, nq = s & 31;
            *(float4*)&Bs[k * BST + nq * 4] =
                *(const float4*)&B[(kb + k) * 128 + nq * 4];
        }
        __syncthreads();

        #pragma unroll
        for (int kk = 0; kk < 4; kk++) {            // 4 k8 steps
            int kof = kk * 8;
            uint32_t a[4][4], b[4][2];
            #pragma unroll
            for (int i = 0; i < 4; i++) {
                int mrow = wm * 64 + i * 16 + grp;
                a[i][0] = __float_as_uint(As[(mrow    ) * AST + kof + tg    ]);
                a[i][1] = __float_as_uint(As[(mrow + 8) * AST + kof + tg    ]);
                a[i][2] = __float_as_uint(As[(mrow    ) * AST + kof + tg + 4]);
                a[i][3] = __float_as_uint(As[(mrow + 8) * AST + kof + tg + 4]);
            }
            #pragma unroll
            for (int j = 0; j < 4; j++) {
                int ncol = wn * 32 + j * 8 + grp;
                b[j][0] = __float_as_uint(Bs[(kof + tg    ) * BST + ncol]);
                b[j][1] = __float_as_uint(Bs[(kof + tg + 4) * BST + ncol]);
            }
            #pragma unroll
            for (int i = 0; i < 4; i++)
                #pragma unroll
                for (int j = 0; j < 4; j++)
                    asm volatile(
                        "mma.sync.aligned.m16n8k8.row.col.f32.tf32.tf32.f32 "
                        "{%0,%1,%2,%3}, {%4,%5,%6,%7}, {%8,%9}, {%0,%1,%2,%3};"
                        : "+f"(c[i][j][0]), "+f"(c[i][j][1]),
                          "+f"(c[i][j][2]), "+f"(c[i][j][3])
                        : "r"(a[i][0]), "r"(a[i][1]), "r"(a[i][2]), "r"(a[i][3]),
                          "r"(b[j][0]), "r"(b[j][1]));
        }
        __syncthreads();
    }

    // epilogue -> H
    float* H = g_H[blockIdx.y];
    #pragma unroll
    for (int i = 0; i < 4; i++) {
        int row0 = m0 + wm * 64 + i * 16 + grp;
        #pragma unroll
        for (int j = 0; j < 4; j++) {
            int ncol = wn * 32 + j * 8 + tg * 2;
            if (row0 < NNODES)
                *(float2*)&H[(size_t)row0 * 128 + ncol] =
                    make_float2(c[i][j][0], c[i][j][1]);
            if (row0 + 8 < NNODES)
                *(float2*)&H[(size_t)(row0 + 8) * 128 + ncol] =
                    make_float2(c[i][j][2], c[i][j][3]);
        }
    }
}

// ---------------------------------------------------------------------------
// Scatter: out[n] (+)= sum over the group's 2 relations of sum_e v * H[src]
// one warp per node, float4 lanes (exact fp32)
// ---------------------------------------------------------------------------
__global__ void __launch_bounds__(256) k_scatter(int g, float* __restrict__ out) {
    int n = blockIdx.x * 8 + (threadIdx.x >> 5);
    int lane = threadIdx.x & 31;
    if (n >= NNODES) return;
    float4* out4 = (float4*)out;
    float4 acc;
    if (g == 0) acc = make_float4(0.f, 0.f, 0.f, 0.f);
    else        acc = out4[(size_t)n * 32 + lane];
    #pragma unroll
    for (int rr = 0; rr < 2; rr++) {
        int idx = (g * 2 + rr) * NNODES + n;
        int j0 = g_off[idx], j1 = g_off[idx + 1];
        const float4* H4 = (const float4*)g_H[rr];
        for (int j = j0; j < j1; j++) {
            int   s = g_esrc[j];
            float v = g_eval[j];
            float4 x = H4[(size_t)s * 32 + lane];
            acc.x += v * x.x; acc.y += v * x.y;
            acc.z += v * x.z; acc.w += v * x.w;
        }
    }
    out4[(size_t)n * 32 + lane] = acc;
}

// ---------------------------------------------------------------------------
// launch
// ---------------------------------------------------------------------------
extern "C" void kernel_launch(void* const* d_in, const int* in_sizes, int n_in,
                              void* d_out, int out_size) {
    const float* inp  = (const float*)d_in[0];
    const int*   src  = (const int*)  d_in[1];
    const int*   dst  = (const int*)  d_in[2];
    const float* vals = (const float*)d_in[3];
    const float* W    = (const float*)d_in[4];
    float* out = (float*)d_out;

    const int SCAN_BLKS = (NIDX + 4095) / 4096;   // 98

    k_prep<<<(INPSZ + 255) / 256, 256>>>(inp, W);
    k_hist<<<(RE + 255) / 256, 256>>>(dst);
    k_scanA<<<SCAN_BLKS, 1024>>>();
    k_scanB<<<1, 128>>>(SCAN_BLKS);
    k_scanC<<<SCAN_BLKS, 1024>>>();
    k_fill<<<(RE + 255) / 256, 256>>>(dst, src, vals);

    for (int g = 0; g < 4; g++) {
        dim3 grid((NNODES + 127) / 128, 2);
        k_gemm<<<grid, 256>>>(g);
        k_scatter<<<(NNODES + 7) / 8, 256>>>(g, out);
    }
}

// round 4
// speedup vs baseline: 2.1608x; 1.1367x over previous
#include <cuda_runtime.h>
#include <cstdint>
#include <cstdio>

#define NNODES 50000
#define NREL   8
#define NEDGES 100000
#define NIDX   (NREL * NNODES)          // 400000
#define RE     (NREL * NEDGES)          // 800000

// ---------------------------------------------------------------------------
// Device scratch
// ---------------------------------------------------------------------------
__device__ float g_H[4][(size_t)NNODES * 128];     // 4 H slabs (102.4 MB)
__device__ int   g_cnt[NIDX];
__device__ int   g_cur[NIDX];
__device__ int   g_off[NIDX + 1];
__device__ int   g_bsum[128];
__device__ int   g_bbase[128];
__device__ int   g_esrc[RE];
__device__ float g_eval[RE];

__device__ __forceinline__ float to_tf32(float x) {
    uint32_t u;
    asm("cvt.rn.tf32.f32 %0, %1;" : "=r"(u) : "f"(x));
    return __uint_as_float(u);
}

// ---------------------------------------------------------------------------
// CSR build kernels
// ---------------------------------------------------------------------------
__global__ void k_zero() {
    int i = blockIdx.x * 256 + threadIdx.x;
    if (i < NIDX) { g_cnt[i] = 0; g_cur[i] = 0; }
}
__global__ void k_hist(const int* __restrict__ dst) {
    int tid = blockIdx.x * 256 + threadIdx.x;
    if (tid >= RE) return;
    int r = tid / NEDGES;
    atomicAdd(&g_cnt[r * NNODES + dst[tid]], 1);
}
__device__ __forceinline__ int wscan(int x, int lane) {
    #pragma unroll
    for (int o = 1; o < 32; o <<= 1) {
        int y = __shfl_up_sync(0xffffffffu, x, o);
        if (lane >= o) x += y;
    }
    return x;
}
__global__ void k_scanA() {
    __shared__ int ws[32];
    int t = threadIdx.x, lane = t & 31, wid = t >> 5;
    int base = blockIdx.x * 4096 + t * 4;
    int v[4];
    #pragma unroll
    for (int i = 0; i < 4; i++) v[i] = (base + i < NIDX) ? g_cnt[base + i] : 0;
    v[1] += v[0]; v[2] += v[1]; v[3] += v[2];
    int x = wscan(v[3], lane);
    if (lane == 31) ws[wid] = x;
    __syncthreads();
    if (wid == 0) ws[lane] = wscan(ws[lane], lane);
    __syncthreads();
    int pre = (wid ? ws[wid - 1] : 0) + (x - v[3]);
    #pragma unroll
    for (int i = 0; i < 4; i++)
        if (base + i < NIDX) g_off[base + i + 1] = pre + v[i];
    if (t == 1023) g_bsum[blockIdx.x] = ws[31];
}
__global__ void k_scanB(int nblk) {
    __shared__ int ws[4];
    int t = threadIdx.x, lane = t & 31, wid = t >> 5;
    int v = (t < nblk) ? g_bsum[t] : 0;
    int x = wscan(v, lane);
    if (lane == 31) ws[wid] = x;
    __syncthreads();
    if (t == 0) { int a = 0; for (int i = 0; i < 4; i++) { int tmp = ws[i]; ws[i] = a; a += tmp; } }
    __syncthreads();
    int incl = x + ws[wid];
    if (t < nblk) g_bbase[t] = incl - v;
}
__global__ void k_scanC() {
    int t = threadIdx.x;
    int add = g_bbase[blockIdx.x];
    int base = blockIdx.x * 4096 + t * 4;
    #pragma unroll
    for (int i = 0; i < 4; i++)
        if (base + i < NIDX) g_off[base + i + 1] += add;
    if (blockIdx.x == 0 && t == 0) g_off[0] = 0;
}
__global__ void k_fill(const int* __restrict__ dst, const int* __restrict__ src,
                       const float* __restrict__ vals) {
    int tid = blockIdx.x * 256 + threadIdx.x;
    if (tid >= RE) return;
    int r = tid / NEDGES;
    int idx = r * NNODES + dst[tid];
    int p = atomicAdd(&g_cur[idx], 1);
    int pos = g_off[idx] + p;
    g_esrc[pos] = src[tid];
    g_eval[pos] = vals[tid];
}

// ---------------------------------------------------------------------------
// GEMM: H[slab] = tf32(inp) @ tf32(W_r)  via mma.sync m16n8k8
// CTA 256 thr = 8 warps (2M x 4N), tile 128x128, BK=32. cvt fused on load.
// ---------------------------------------------------------------------------
#define AST 36
#define BST 136

__global__ void __launch_bounds__(256) k_gemm(int g, const float* __restrict__ inp,
                                              const float* __restrict__ W) {
    __shared__ __align__(16) float As[128 * AST];
    __shared__ __align__(16) float Bs[32 * BST];

    int tid = threadIdx.x;
    int lane = tid & 31, wid = tid >> 5;
    int grp = lane >> 2, tg = lane & 3;
    int wm = wid & 1, wn = wid >> 1;
    int m0 = blockIdx.x * 128;
    int r  = g * 2 + blockIdx.y;

    const float* B = W + r * 16384;

    float c[4][4][4];
    #pragma unroll
    for (int i = 0; i < 4; i++)
        #pragma unroll
        for (int j = 0; j < 4; j++)
            c[i][j][0] = c[i][j][1] = c[i][j][2] = c[i][j][3] = 0.f;

    for (int kb = 0; kb < 128; kb += 32) {
        #pragma unroll
        for (int it = 0; it < 4; it++) {
            int s = it * 256 + tid;
            int m = s >> 3, kq = s & 7;
            int grow = m0 + m;
            float4 v = make_float4(0.f, 0.f, 0.f, 0.f);
            if (grow < NNODES)
                v = *(const float4*)&inp[(size_t)grow * 128 + kb + kq * 4];
            v.x = to_tf32(v.x); v.y = to_tf32(v.y);
            v.z = to_tf32(v.z); v.w = to_tf32(v.w);
            *(float4*)&As[m * AST + kq * 4] = v;
        }
        #pragma unroll
        for (int it = 0; it < 4; it++) {
            int s = it * 256 + tid;
            int k = s >> 5, nq = s & 31;
            float4 w = *(const float4*)&B[(kb + k) * 128 + nq * 4];
            w.x = to_tf32(w.x); w.y = to_tf32(w.y);
            w.z = to_tf32(w.z); w.w = to_tf32(w.w);
            *(float4*)&Bs[k * BST + nq * 4] = w;
        }
        __syncthreads();

        #pragma unroll
        for (int kk = 0; kk < 4; kk++) {
            int kof = kk * 8;
            uint32_t a[4][4], b[4][2];
            #pragma unroll
            for (int i = 0; i < 4; i++) {
                int mrow = wm * 64 + i * 16 + grp;
                a[i][0] = __float_as_uint(As[(mrow    ) * AST + kof + tg    ]);
                a[i][1] = __float_as_uint(As[(mrow + 8) * AST + kof + tg    ]);
                a[i][2] = __float_as_uint(As[(mrow    ) * AST + kof + tg + 4]);
                a[i][3] = __float_as_uint(As[(mrow + 8) * AST + kof + tg + 4]);
            }
            #pragma unroll
            for (int j = 0; j < 4; j++) {
                int ncol = wn * 32 + j * 8 + grp;
                b[j][0] = __float_as_uint(Bs[(kof + tg    ) * BST + ncol]);
                b[j][1] = __float_as_uint(Bs[(kof + tg + 4) * BST + ncol]);
            }
            #pragma unroll
            for (int i = 0; i < 4; i++)
                #pragma unroll
                for (int j = 0; j < 4; j++)
                    asm volatile(
                        "mma.sync.aligned.m16n8k8.row.col.f32.tf32.tf32.f32 "
                        "{%0,%1,%2,%3}, {%4,%5,%6,%7}, {%8,%9}, {%0,%1,%2,%3};"
                        : "+f"(c[i][j][0]), "+f"(c[i][j][1]),
                          "+f"(c[i][j][2]), "+f"(c[i][j][3])
                        : "r"(a[i][0]), "r"(a[i][1]), "r"(a[i][2]), "r"(a[i][3]),
                          "r"(b[j][0]), "r"(b[j][1]));
        }
        __syncthreads();
    }

    float* H = g_H[2 * (g & 1) + blockIdx.y];
    #pragma unroll
    for (int i = 0; i < 4; i++) {
        int row0 = m0 + wm * 64 + i * 16 + grp;
        #pragma unroll
        for (int j = 0; j < 4; j++) {
            int ncol = wn * 32 + j * 8 + tg * 2;
            if (row0 < NNODES)
                *(float2*)&H[(size_t)row0 * 128 + ncol] =
                    make_float2(c[i][j][0], c[i][j][1]);
            if (row0 + 8 < NNODES)
                *(float2*)&H[(size_t)(row0 + 8) * 128 + ncol] =
                    make_float2(c[i][j][2], c[i][j][3]);
        }
    }
}

// ---------------------------------------------------------------------------
// Scatter: out[n] (+)= sum over 2 relations of sum_e v * H[src], x2 unrolled
// ---------------------------------------------------------------------------
__global__ void __launch_bounds__(256) k_scatter(int g, float* __restrict__ out) {
    int n = blockIdx.x * 8 + (threadIdx.x >> 5);
    int lane = threadIdx.x & 31;
    if (n >= NNODES) return;
    float4* out4 = (float4*)out;
    float4 acc;
    if (g == 0) acc = make_float4(0.f, 0.f, 0.f, 0.f);
    else        acc = out4[(size_t)n * 32 + lane];
    #pragma unroll
    for (int rr = 0; rr < 2; rr++) {
        int idx = (g * 2 + rr) * NNODES + n;
        int j0 = g_off[idx], j1 = g_off[idx + 1];
        const float4* H4 = (const float4*)g_H[2 * (g & 1) + rr];
        int j = j0;
        for (; j + 1 < j1; j += 2) {
            int   s0 = g_esrc[j],     s1 = g_esrc[j + 1];
            float v0 = g_eval[j],     v1 = g_eval[j + 1];
            float4 x0 = H4[(size_t)s0 * 32 + lane];
            float4 x1 = H4[(size_t)s1 * 32 + lane];
            acc.x += v0 * x0.x; acc.y += v0 * x0.y;
            acc.z += v0 * x0.z; acc.w += v0 * x0.w;
            acc.x += v1 * x1.x; acc.y += v1 * x1.y;
            acc.z += v1 * x1.z; acc.w += v1 * x1.w;
        }
        if (j < j1) {
            int   s = g_esrc[j];
            float v = g_eval[j];
            float4 x = H4[(size_t)s * 32 + lane];
            acc.x += v * x.x; acc.y += v * x.y;
            acc.z += v * x.z; acc.w += v * x.w;
        }
    }
    out4[(size_t)n * 32 + lane] = acc;
}

// ---------------------------------------------------------------------------
// Streams/events: created once, pre-main (host objects only; no device mem
// inside kernel_launch). Fallback to single-stream if creation fails.
// ---------------------------------------------------------------------------
static cudaStream_t s2 = nullptr;
static cudaEvent_t  evFork, evG[4], evS[4], evJoin;
static bool g_ok = false;

namespace {
struct StreamInit {
    StreamInit() {
        if (cudaStreamCreateWithFlags(&s2, cudaStreamNonBlocking) != cudaSuccess) return;
        if (cudaEventCreateWithFlags(&evFork, cudaEventDisableTiming) != cudaSuccess) return;
        if (cudaEventCreateWithFlags(&evJoin, cudaEventDisableTiming) != cudaSuccess) return;
        for (int i = 0; i < 4; i++) {
            if (cudaEventCreateWithFlags(&evG[i], cudaEventDisableTiming) != cudaSuccess) return;
            if (cudaEventCreateWithFlags(&evS[i], cudaEventDisableTiming) != cudaSuccess) return;
        }
        g_ok = true;
    }
};
static StreamInit g_si;
}

extern "C" void kernel_launch(void* const* d_in, const int* in_sizes, int n_in,
                              void* d_out, int out_size) {
    const float* inp  = (const float*)d_in[0];
    const int*   src  = (const int*)  d_in[1];
    const int*   dst  = (const int*)  d_in[2];
    const float* vals = (const float*)d_in[3];
    const float* W    = (const float*)d_in[4];
    float* out = (float*)d_out;

    const int SCAN_BLKS = (NIDX + 4095) / 4096;   // 98
    dim3 ggrid((NNODES + 127) / 128, 2);
    int  sgrid = (NNODES + 7) / 8;

    if (g_ok) {
        // fork: CSR build on s2, GEMMs on capture (default) stream
        cudaEventRecord(evFork, 0);
        cudaStreamWaitEvent(s2, evFork, 0);

        k_zero <<<(NIDX + 255) / 256, 256, 0, s2>>>();
        k_hist <<<(RE + 255) / 256, 256, 0, s2>>>(dst);
        k_scanA<<<SCAN_BLKS, 1024, 0, s2>>>();
        k_scanB<<<1, 128, 0, s2>>>(SCAN_BLKS);
        k_scanC<<<SCAN_BLKS, 1024, 0, s2>>>();
        k_fill <<<(RE + 255) / 256, 256, 0, s2>>>(dst, src, vals);

        k_gemm<<<ggrid, 256>>>(0, inp, W);
        cudaEventRecord(evG[0], 0);
        k_gemm<<<ggrid, 256>>>(1, inp, W);
        cudaEventRecord(evG[1], 0);

        cudaStreamWaitEvent(s2, evG[0], 0);
        k_scatter<<<sgrid, 256, 0, s2>>>(0, out);
        cudaEventRecord(evS[0], s2);

        cudaStreamWaitEvent(0, evS[0], 0);      // WAR: gemm2 reuses slab pair 0
        k_gemm<<<ggrid, 256>>>(2, inp, W);
        cudaEventRecord(evG[2], 0);

        cudaStreamWaitEvent(s2, evG[1], 0);
        k_scatter<<<sgrid, 256, 0, s2>>>(1, out);
        cudaEventRecord(evS[1], s2);

        cudaStreamWaitEvent(0, evS[1], 0);      // WAR: gemm3 reuses slab pair 1
        k_gemm<<<ggrid, 256>>>(3, inp, W);
        cudaEventRecord(evG[3], 0);

        cudaStreamWaitEvent(s2, evG[2], 0);
        k_scatter<<<sgrid, 256, 0, s2>>>(2, out);
        cudaStreamWaitEvent(s2, evG[3], 0);
        k_scatter<<<sgrid, 256, 0, s2>>>(3, out);
        cudaEventRecord(evJoin, s2);

        cudaStreamWaitEvent(0, evJoin, 0);      // join back to capture stream
    } else {
        // sequential fallback
        k_zero <<<(NIDX + 255) / 256, 256>>>();
        k_hist <<<(RE + 255) / 256, 256>>>(dst);
        k_scanA<<<SCAN_BLKS, 1024>>>();
        k_scanB<<<1, 128>>>(SCAN_BLKS);
        k_scanC<<<SCAN_BLKS, 1024>>>();
        k_fill <<<(RE + 255) / 256, 256>>>(dst, src, vals);
        for (int g = 0; g < 4; g++) {
            k_gemm<<<ggrid, 256>>>(g, inp, W);
            k_scatter<<<sgrid, 256>>>(g, out);
        }
    }
}

// round 5
// speedup vs baseline: 2.1917x; 1.0143x over previous
#include <cuda_runtime.h>
#include <cuda_fp16.h>
#include <cstdint>

#define NNODES 50000
#define NREL   8
#define NEDGES 100000
#define NIDX   (NREL * NNODES)          // 400000
#define RE     (NREL * NEDGES)          // 800000
#define INPSZ  (NNODES * 128)

// ---------------------------------------------------------------------------
// Device scratch
// ---------------------------------------------------------------------------
__device__ float  g_inp_tf[(size_t)INPSZ];            // tf32-rounded inp
__device__ float  g_Wtf[NREL * 128 * 128];            // tf32-rounded W
__device__ __half g_Hh[NREL][(size_t)NNODES * 128];   // H in fp16 (102.4 MB)
__device__ int    g_cnt[NIDX];
__device__ int    g_cur[NIDX];
__device__ int    g_off[NIDX + 1];
__device__ int    g_bsum[128];
__device__ int    g_bbase[128];
__device__ int    g_esrc[RE];
__device__ float  g_eval[RE];

__device__ __forceinline__ float to_tf32(float x) {
    uint32_t u;
    asm("cvt.rn.tf32.f32 %0, %1;" : "=r"(u) : "f"(x));
    return __uint_as_float(u);
}
__device__ __forceinline__ uint32_t smem_u32(const void* p) {
    uint32_t a;
    asm("{ .reg .u64 t; cvta.to.shared.u64 t, %1; cvt.u32.u64 %0, t; }" : "=r"(a) : "l"(p));
    return a;
}
__device__ __forceinline__ void cp16(uint32_t dst, const void* src, uint32_t bytes) {
    asm volatile("cp.async.cg.shared.global [%0], [%1], 16, %2;"
                 :: "r"(dst), "l"(src), "r"(bytes) : "memory");
}

// ---------------------------------------------------------------------------
// Prep: round inp + W to tf32 (runs before GEMM on main stream)
// ---------------------------------------------------------------------------
__global__ void k_prep(const float* __restrict__ inp, const float* __restrict__ W) {
    int i = blockIdx.x * 256 + threadIdx.x;
    if (i < INPSZ)            g_inp_tf[i] = to_tf32(inp[i]);
    if (i < NREL * 128 * 128) g_Wtf[i]    = to_tf32(W[i]);
}

// ---------------------------------------------------------------------------
// CSR build (side stream)
// ---------------------------------------------------------------------------
__global__ void k_zero() {
    int i = blockIdx.x * 256 + threadIdx.x;
    if (i < NIDX) { g_cnt[i] = 0; g_cur[i] = 0; }
}
__global__ void k_hist(const int* __restrict__ dst) {
    int tid = blockIdx.x * 256 + threadIdx.x;
    if (tid >= RE) return;
    int r = tid / NEDGES;
    atomicAdd(&g_cnt[r * NNODES + dst[tid]], 1);
}
__device__ __forceinline__ int wscan(int x, int lane) {
    #pragma unroll
    for (int o = 1; o < 32; o <<= 1) {
        int y = __shfl_up_sync(0xffffffffu, x, o);
        if (lane >= o) x += y;
    }
    return x;
}
__global__ void k_scanA() {
    __shared__ int ws[32];
    int t = threadIdx.x, lane = t & 31, wid = t >> 5;
    int base = blockIdx.x * 4096 + t * 4;
    int v[4];
    #pragma unroll
    for (int i = 0; i < 4; i++) v[i] = (base + i < NIDX) ? g_cnt[base + i] : 0;
    v[1] += v[0]; v[2] += v[1]; v[3] += v[2];
    int x = wscan(v[3], lane);
    if (lane == 31) ws[wid] = x;
    __syncthreads();
    if (wid == 0) ws[lane] = wscan(ws[lane], lane);
    __syncthreads();
    int pre = (wid ? ws[wid - 1] : 0) + (x - v[3]);
    #pragma unroll
    for (int i = 0; i < 4; i++)
        if (base + i < NIDX) g_off[base + i + 1] = pre + v[i];
    if (t == 1023) g_bsum[blockIdx.x] = ws[31];
}
__global__ void k_scanB(int nblk) {
    __shared__ int ws[4];
    int t = threadIdx.x, lane = t & 31, wid = t >> 5;
    int v = (t < nblk) ? g_bsum[t] : 0;
    int x = wscan(v, lane);
    if (lane == 31) ws[wid] = x;
    __syncthreads();
    if (t == 0) { int a = 0; for (int i = 0; i < 4; i++) { int tmp = ws[i]; ws[i] = a; a += tmp; } }
    __syncthreads();
    int incl = x + ws[wid];
    if (t < nblk) g_bbase[t] = incl - v;
}
__global__ void k_scanC() {
    int t = threadIdx.x;
    int add = g_bbase[blockIdx.x];
    int base = blockIdx.x * 4096 + t * 4;
    #pragma unroll
    for (int i = 0; i < 4; i++)
        if (base + i < NIDX) g_off[base + i + 1] += add;
    if (blockIdx.x == 0 && t == 0) g_off[0] = 0;
}
__global__ void k_fill(const int* __restrict__ dst, const int* __restrict__ src,
                       const float* __restrict__ vals) {
    int tid = blockIdx.x * 256 + threadIdx.x;
    if (tid >= RE) return;
    int r = tid / NEDGES;
    int idx = r * NNODES + dst[tid];
    int p = atomicAdd(&g_cur[idx], 1);
    int pos = g_off[idx] + p;
    g_esrc[pos] = src[tid];
    g_eval[pos] = vals[tid];
}

// ---------------------------------------------------------------------------
// GEMM: H[r] = inp_tf @ W_r  (all 8 relations in one launch)
// m16n8k8 tf32 mma, CTA tile 128x128, BK=16, 2-stage cp.async pipeline.
// 8 warps (2M x 4N), warp tile 64x32, 2 CTAs/SM.
// ---------------------------------------------------------------------------
#define AST 20    // As row stride: banks (20g+t)%32 all distinct
#define BST 136   // Bs row stride: banks (8t+g)%32 all distinct

__global__ void __launch_bounds__(256, 2) k_gemm() {
    __shared__ __align__(16) float As[2][128 * AST];   // 2 x 10240 B
    __shared__ __align__(16) float Bs[2][16 * BST];    // 2 x  8704 B

    int tid = threadIdx.x;
    int lane = tid & 31, wid = tid >> 5;
    int grp = lane >> 2, tg = lane & 3;
    int wm = wid & 1, wn = wid >> 1;
    int m0 = blockIdx.x * 128;
    int r  = blockIdx.y;

    const float* A = g_inp_tf;
    const float* B = g_Wtf + r * 16384;

    // per-thread cp.async coordinates
    int am = tid >> 1, akq = (tid & 1) * 2;        // A: 128 rows x 4 f4 -> 2/thread
    int bk = tid >> 4, bnq = (tid & 15) * 2;       // B: 16 rows x 32 f4 -> 2/thread

    uint32_t asb[2], bsb[2];
    asb[0] = smem_u32(&As[0][0]); asb[1] = smem_u32(&As[1][0]);
    bsb[0] = smem_u32(&Bs[0][0]); bsb[1] = smem_u32(&Bs[1][0]);

    int grow = m0 + am;
    uint32_t abytes = (grow < NNODES) ? 16u : 0u;
    const float* aptr = &A[(size_t)(grow < NNODES ? grow : 0) * 128 + akq * 4];
    const float* bptr = &B[bk * 128 + bnq * 4];

    // prologue: stage 0 <- kb 0
    #pragma unroll
    for (int q = 0; q < 2; q++) {
        cp16(asb[0] + (am * AST + (akq + q) * 4) * 4, aptr + q * 4, abytes);
        cp16(bsb[0] + (bk * BST + (bnq + q) * 4) * 4, bptr + q * 4, 16u);
    }
    asm volatile("cp.async.commit_group;" ::: "memory");

    float c[4][4][4];
    #pragma unroll
    for (int i = 0; i < 4; i++)
        #pragma unroll
        for (int j = 0; j < 4; j++)
            c[i][j][0] = c[i][j][1] = c[i][j][2] = c[i][j][3] = 0.f;

    int st = 0;
    for (int kb = 0; kb < 8; kb++) {
        asm volatile("cp.async.wait_group 0;" ::: "memory");
        __syncthreads();
        if (kb < 7) {
            int kn = (kb + 1) * 16;
            #pragma unroll
            for (int q = 0; q < 2; q++) {
                cp16(asb[st ^ 1] + (am * AST + (akq + q) * 4) * 4,
                     aptr + kn + q * 4, abytes);
                cp16(bsb[st ^ 1] + (bk * BST + (bnq + q) * 4) * 4,
                     bptr + kn * 128 + q * 4, 16u);
            }
            asm volatile("cp.async.commit_group;" ::: "memory");
        }
        const float* as = As[st];
        const float* bs = Bs[st];
        #pragma unroll
        for (int kk = 0; kk < 2; kk++) {
            int kof = kk * 8;
            uint32_t a[4][4], b[4][2];
            #pragma unroll
            for (int i = 0; i < 4; i++) {
                int mrow = wm * 64 + i * 16 + grp;
                a[i][0] = __float_as_uint(as[(mrow    ) * AST + kof + tg    ]);
                a[i][1] = __float_as_uint(as[(mrow + 8) * AST + kof + tg    ]);
                a[i][2] = __float_as_uint(as[(mrow    ) * AST + kof + tg + 4]);
                a[i][3] = __float_as_uint(as[(mrow + 8) * AST + kof + tg + 4]);
            }
            #pragma unroll
            for (int j = 0; j < 4; j++) {
                int ncol = wn * 32 + j * 8 + grp;
                b[j][0] = __float_as_uint(bs[(kof + tg    ) * BST + ncol]);
                b[j][1] = __float_as_uint(bs[(kof + tg + 4) * BST + ncol]);
            }
            #pragma unroll
            for (int i = 0; i < 4; i++)
                #pragma unroll
                for (int j = 0; j < 4; j++)
                    asm volatile(
                        "mma.sync.aligned.m16n8k8.row.col.f32.tf32.tf32.f32 "
                        "{%0,%1,%2,%3}, {%4,%5,%6,%7}, {%8,%9}, {%0,%1,%2,%3};"
                        : "+f"(c[i][j][0]), "+f"(c[i][j][1]),
                          "+f"(c[i][j][2]), "+f"(c[i][j][3])
                        : "r"(a[i][0]), "r"(a[i][1]), "r"(a[i][2]), "r"(a[i][3]),
                          "r"(b[j][0]), "r"(b[j][1]));
        }
        st ^= 1;
        __syncthreads();
    }

    // epilogue -> fp16 H (half2 stores)
    uint32_t* H = (uint32_t*)g_Hh[r];
    #pragma unroll
    for (int i = 0; i < 4; i++) {
        int row0 = m0 + wm * 64 + i * 16 + grp;
        #pragma unroll
        for (int j = 0; j < 4; j++) {
            int nc2 = (wn * 32 + j * 8 + tg * 2) >> 1;   // half2 index
            __half2 lo = __floats2half2_rn(c[i][j][0], c[i][j][1]);
            __half2 hi = __floats2half2_rn(c[i][j][2], c[i][j][3]);
            if (row0 < NNODES)
                H[(size_t)row0 * 64 + nc2] = *(uint32_t*)&lo;
            if (row0 + 8 < NNODES)
                H[(size_t)(row0 + 8) * 64 + nc2] = *(uint32_t*)&hi;
        }
    }
}

// ---------------------------------------------------------------------------
// Scatter: out[n] = sum_r sum_e v * H_r[src]   (fp16 gather, fp32 accumulate)
// warp per node, lane covers 4 output cols
// ---------------------------------------------------------------------------
__global__ void __launch_bounds__(256) k_scatter(float* __restrict__ out) {
    int n = blockIdx.x * 8 + (threadIdx.x >> 5);
    int lane = threadIdx.x & 31;
    if (n >= NNODES) return;
    float4 acc = make_float4(0.f, 0.f, 0.f, 0.f);
    #pragma unroll
    for (int r = 0; r < NREL; r++) {
        int idx = r * NNODES + n;
        int j0 = g_off[idx], j1 = g_off[idx + 1];
        const uint2* H2 = (const uint2*)g_Hh[r];
        int j = j0;
        for (; j + 1 < j1; j += 2) {
            int   s0 = g_esrc[j],  s1 = g_esrc[j + 1];
            float v0 = g_eval[j],  v1 = g_eval[j + 1];
            uint2 p0 = H2[(size_t)s0 * 32 + lane];
            uint2 p1 = H2[(size_t)s1 * 32 + lane];
            float2 x0 = __half22float2(*(__half2*)&p0.x);
            float2 y0 = __half22float2(*(__half2*)&p0.y);
            float2 x1 = __half22float2(*(__half2*)&p1.x);
            float2 y1 = __half22float2(*(__half2*)&p1.y);
            acc.x += v0 * x0.x + v1 * x1.x;
            acc.y += v0 * x0.y + v1 * x1.y;
            acc.z += v0 * y0.x + v1 * y1.x;
            acc.w += v0 * y0.y + v1 * y1.y;
        }
        if (j < j1) {
            int   s = g_esrc[j];
            float v = g_eval[j];
            uint2 p = H2[(size_t)s * 32 + lane];
            float2 x = __half22float2(*(__half2*)&p.x);
            float2 y = __half22float2(*(__half2*)&p.y);
            acc.x += v * x.x; acc.y += v * x.y;
            acc.z += v * y.x; acc.w += v * y.y;
        }
    }
    ((float4*)out)[(size_t)n * 32 + lane] = acc;
}

// ---------------------------------------------------------------------------
// Streams/events (host objects, created pre-main)
// ---------------------------------------------------------------------------
static cudaStream_t s2 = nullptr;
static cudaEvent_t  evFork, evFill;
static bool g_ok = false;

namespace {
struct StreamInit {
    StreamInit() {
        if (cudaStreamCreateWithFlags(&s2, cudaStreamNonBlocking) != cudaSuccess) return;
        if (cudaEventCreateWithFlags(&evFork, cudaEventDisableTiming) != cudaSuccess) return;
        if (cudaEventCreateWithFlags(&evFill, cudaEventDisableTiming) != cudaSuccess) return;
        g_ok = true;
    }
};
static StreamInit g_si;
}

extern "C" void kernel_launch(void* const* d_in, const int* in_sizes, int n_in,
                              void* d_out, int out_size) {
    const float* inp  = (const float*)d_in[0];
    const int*   src  = (const int*)  d_in[1];
    const int*   dst  = (const int*)  d_in[2];
    const float* vals = (const float*)d_in[3];
    const float* W    = (const float*)d_in[4];
    float* out = (float*)d_out;

    const int SCAN_BLKS = (NIDX + 4095) / 4096;   // 98
    dim3 ggrid((NNODES + 127) / 128, NREL);       // 391 x 8
    int  sgrid = (NNODES + 7) / 8;

    if (g_ok) {
        cudaEventRecord(evFork, 0);
        cudaStreamWaitEvent(s2, evFork, 0);

        // side stream: CSR build
        k_zero <<<(NIDX + 255) / 256, 256, 0, s2>>>();
        k_hist <<<(RE + 255) / 256, 256, 0, s2>>>(dst);
        k_scanA<<<SCAN_BLKS, 1024, 0, s2>>>();
        k_scanB<<<1, 128, 0, s2>>>(SCAN_BLKS);
        k_scanC<<<SCAN_BLKS, 1024, 0, s2>>>();
        k_fill <<<(RE + 255) / 256, 256, 0, s2>>>(dst, src, vals);
        cudaEventRecord(evFill, s2);

        // main stream: prep -> gemm -> (wait fill) -> scatter
        k_prep<<<(INPSZ + 255) / 256, 256>>>(inp, W);
        k_gemm<<<ggrid, 256>>>();
        cudaStreamWaitEvent(0, evFill, 0);
        k_scatter<<<sgrid, 256>>>(out);
    } else {
        k_prep <<<(INPSZ + 255) / 256, 256>>>(inp, W);
        k_zero <<<(NIDX + 255) / 256, 256>>>();
        k_hist <<<(RE + 255) / 256, 256>>>(dst);
        k_scanA<<<SCAN_BLKS, 1024>>>();
        k_scanB<<<1, 128>>>(SCAN_BLKS);
        k_scanC<<<SCAN_BLKS, 1024>>>();
        k_fill <<<(RE + 255) / 256, 256>>>(dst, src, vals);
        k_gemm<<<ggrid, 256>>>();
        k_scatter<<<sgrid, 256>>>(out);
    }
}

// round 6
// speedup vs baseline: 3.0454x; 1.3895x over previous
#include <cuda_runtime.h>
#include <cuda_fp16.h>
#include <cstdint>

#define NNODES 50000
#define NREL   8
#define NEDGES 100000
#define NIDX   (NREL * NNODES)          // 400000
#define RE     (NREL * NEDGES)          // 800000
#define INPSZ  (NNODES * 128)
#define WSZ    (NREL * 128 * 128)

// ---------------------------------------------------------------------------
// Device scratch
// ---------------------------------------------------------------------------
__device__ __half g_inph[(size_t)INPSZ];              // fp16 inp (12.8 MB)
__device__ __half g_Wh[WSZ];                          // fp16 W
__device__ __half g_Hh[NREL][(size_t)NNODES * 128];   // fp16 H (102.4 MB)
__device__ int    g_cnt[NIDX];
__device__ int    g_cur[NIDX];
__device__ int    g_off[NIDX + 1];
__device__ int    g_bsum[128];
__device__ int    g_bbase[128];
__device__ int    g_esrc[RE];
__device__ float  g_eval[RE];

__device__ __forceinline__ uint32_t smem_u32(const void* p) {
    uint32_t a;
    asm("{ .reg .u64 t; cvta.to.shared.u64 t, %1; cvt.u32.u64 %0, t; }" : "=r"(a) : "l"(p));
    return a;
}
__device__ __forceinline__ void cp16(uint32_t dst, const void* src, uint32_t bytes) {
    asm volatile("cp.async.cg.shared.global [%0], [%1], 16, %2;"
                 :: "r"(dst), "l"(src), "r"(bytes) : "memory");
}

// ---------------------------------------------------------------------------
// Prep: fp32 -> fp16 for inp and W
// ---------------------------------------------------------------------------
__global__ void k_prep(const float2* __restrict__ inp, const float2* __restrict__ W) {
    int i = blockIdx.x * 256 + threadIdx.x;
    if (i < INPSZ / 2) {
        float2 v = inp[i];
        ((__half2*)g_inph)[i] = __floats2half2_rn(v.x, v.y);
    }
    if (i < WSZ / 2) {
        float2 w = W[i];
        ((__half2*)g_Wh)[i] = __floats2half2_rn(w.x, w.y);
    }
}

// ---------------------------------------------------------------------------
// CSR build (side stream)
// ---------------------------------------------------------------------------
__global__ void k_zero() {
    int i = blockIdx.x * 256 + threadIdx.x;
    if (i < NIDX) { g_cnt[i] = 0; g_cur[i] = 0; }
}
__global__ void k_hist(const int* __restrict__ dst) {
    int tid = blockIdx.x * 256 + threadIdx.x;
    if (tid >= RE) return;
    int r = tid / NEDGES;
    atomicAdd(&g_cnt[r * NNODES + dst[tid]], 1);
}
__device__ __forceinline__ int wscan(int x, int lane) {
    #pragma unroll
    for (int o = 1; o < 32; o <<= 1) {
        int y = __shfl_up_sync(0xffffffffu, x, o);
        if (lane >= o) x += y;
    }
    return x;
}
__global__ void k_scanA() {
    __shared__ int ws[32];
    int t = threadIdx.x, lane = t & 31, wid = t >> 5;
    int base = blockIdx.x * 4096 + t * 4;
    int v[4];
    #pragma unroll
    for (int i = 0; i < 4; i++) v[i] = (base + i < NIDX) ? g_cnt[base + i] : 0;
    v[1] += v[0]; v[2] += v[1]; v[3] += v[2];
    int x = wscan(v[3], lane);
    if (lane == 31) ws[wid] = x;
    __syncthreads();
    if (wid == 0) ws[lane] = wscan(ws[lane], lane);
    __syncthreads();
    int pre = (wid ? ws[wid - 1] : 0) + (x - v[3]);
    #pragma unroll
    for (int i = 0; i < 4; i++)
        if (base + i < NIDX) g_off[base + i + 1] = pre + v[i];
    if (t == 1023) g_bsum[blockIdx.x] = ws[31];
}
__global__ void k_scanB(int nblk) {
    __shared__ int ws[4];
    int t = threadIdx.x, lane = t & 31, wid = t >> 5;
    int v = (t < nblk) ? g_bsum[t] : 0;
    int x = wscan(v, lane);
    if (lane == 31) ws[wid] = x;
    __syncthreads();
    if (t == 0) { int a = 0; for (int i = 0; i < 4; i++) { int tmp = ws[i]; ws[i] = a; a += tmp; } }
    __syncthreads();
    int incl = x + ws[wid];
    if (t < nblk) g_bbase[t] = incl - v;
}
__global__ void k_scanC() {
    int t = threadIdx.x;
    int add = g_bbase[blockIdx.x];
    int base = blockIdx.x * 4096 + t * 4;
    #pragma unroll
    for (int i = 0; i < 4; i++)
        if (base + i < NIDX) g_off[base + i + 1] += add;
    if (blockIdx.x == 0 && t == 0) g_off[0] = 0;
}
__global__ void k_fill(const int* __restrict__ dst, const int* __restrict__ src,
                       const float* __restrict__ vals) {
    int tid = blockIdx.x * 256 + threadIdx.x;
    if (tid >= RE) return;
    int r = tid / NEDGES;
    int idx = r * NNODES + dst[tid];
    int p = atomicAdd(&g_cur[idx], 1);
    int pos = g_off[idx] + p;
    g_esrc[pos] = src[tid];
    g_eval[pos] = vals[tid];
}

// ---------------------------------------------------------------------------
// GEMM: H[r] = inp_h @ W_r  via mma.sync m16n8k16 fp16 (fp32 accum)
// CTA tile 128x128, BK=32, 2-stage cp.async. 8 warps (2M x 4N), 64x32/warp.
// A tile: [128][40] halves (pad 40 -> ldmatrix conflict-free).
// B tile: [32][128] halves, 16B-column XOR swizzle (col ^ (k&7)).
// ---------------------------------------------------------------------------
__global__ void __launch_bounds__(256, 2) k_gemm() {
    __shared__ __align__(16) __half As[2][128 * 40];   // 2 x 10240 B
    __shared__ __align__(16) __half Bs[2][32 * 128];   // 2 x  8192 B

    int tid = threadIdx.x;
    int lane = tid & 31, wid = tid >> 5;
    int wm = wid & 1, wn = wid >> 1;
    int m0 = blockIdx.x * 128;
    int r  = blockIdx.y;

    const __half* A = g_inph;
    const __half* B = g_Wh + r * 16384;

    uint32_t asb[2] = { smem_u32(As[0]), smem_u32(As[1]) };
    uint32_t bsb[2] = { smem_u32(Bs[0]), smem_u32(Bs[1]) };

    // cp.async coordinates (2 x 16B chunks of A and of B per thread)
    int am  = tid >> 1;                 // A row 0..127
    int aq  = (tid & 1) * 2;            // A 16B-chunk (k/8): aq, aq+1
    int bkr = tid >> 3;                 // B row 0..31
    int bc  = (tid & 7) * 2;            // B 16B-col: bc, bc+1

    int grow = m0 + am;
    uint32_t abytes = (grow < NNODES) ? 16u : 0u;
    const __half* aptr = A + (size_t)(grow < NNODES ? grow : 0) * 128 + aq * 8;
    const __half* bptr = B + bkr * 128 + bc * 8;

    uint32_t aoff = (uint32_t)(am * 80 + aq * 16);
    uint32_t boff0 = (uint32_t)(bkr * 256 + ((bc    ) ^ (bkr & 7)) * 16);
    uint32_t boff1 = (uint32_t)(bkr * 256 + ((bc + 1) ^ (bkr & 7)) * 16);

    // prologue: stage 0 <- k-halves [0,32)
    cp16(asb[0] + aoff,      aptr,     abytes);
    cp16(asb[0] + aoff + 16, aptr + 8, abytes);
    cp16(bsb[0] + boff0, bptr,     16u);
    cp16(bsb[0] + boff1, bptr + 8, 16u);
    asm volatile("cp.async.commit_group;" ::: "memory");

    // ldmatrix per-lane address pieces
    uint32_t arow = (uint32_t)(wm * 64 + (lane & 7) + ((lane >> 3) & 1) * 8);
    uint32_t aoff_l = arow * 80 + (lane >> 4) * 16;       // + i*16*80 + kk*32
    uint32_t bkrow = (uint32_t)(lane & 15);               // + kk*16
    uint32_t bcol[2];
    bcol[0] = (uint32_t)(((wn * 4 + 0 + (lane >> 4)) ^ (lane & 7)) * 16);
    bcol[1] = (uint32_t)(((wn * 4 + 2 + (lane >> 4)) ^ (lane & 7)) * 16);

    float c[4][4][4];
    #pragma unroll
    for (int i = 0; i < 4; i++)
        #pragma unroll
        for (int j = 0; j < 4; j++)
            c[i][j][0] = c[i][j][1] = c[i][j][2] = c[i][j][3] = 0.f;

    int st = 0;
    for (int kb = 0; kb < 4; kb++) {
        asm volatile("cp.async.wait_group 0;" ::: "memory");
        __syncthreads();
        if (kb < 3) {
            int kn = (kb + 1) * 32;
            cp16(asb[st ^ 1] + aoff,      aptr + kn,     abytes);
            cp16(asb[st ^ 1] + aoff + 16, aptr + kn + 8, abytes);
            cp16(bsb[st ^ 1] + boff0, bptr + kn * 128,     16u);
            cp16(bsb[st ^ 1] + boff1, bptr + kn * 128 + 8, 16u);
            asm volatile("cp.async.commit_group;" ::: "memory");
        }
        #pragma unroll
        for (int kk = 0; kk < 2; kk++) {
            uint32_t a[4][4], b[4][2];
            #pragma unroll
            for (int i = 0; i < 4; i++) {
                uint32_t ad = asb[st] + aoff_l + (uint32_t)(i * 16 * 80) + kk * 32;
                asm volatile("ldmatrix.sync.aligned.m8n8.x4.shared.b16 "
                             "{%0,%1,%2,%3}, [%4];"
                             : "=r"(a[i][0]), "=r"(a[i][1]), "=r"(a[i][2]), "=r"(a[i][3])
                             : "r"(ad));
            }
            #pragma unroll
            for (int p = 0; p < 2; p++) {
                uint32_t bd = bsb[st] + (kk * 16 + bkrow) * 256 + bcol[p];
                asm volatile("ldmatrix.sync.aligned.m8n8.x4.trans.shared.b16 "
                             "{%0,%1,%2,%3}, [%4];"
                             : "=r"(b[p*2][0]), "=r"(b[p*2][1]),
                               "=r"(b[p*2+1][0]), "=r"(b[p*2+1][1])
                             : "r"(bd));
            }
            #pragma unroll
            for (int i = 0; i < 4; i++)
                #pragma unroll
                for (int j = 0; j < 4; j++)
                    asm volatile(
                        "mma.sync.aligned.m16n8k16.row.col.f32.f16.f16.f32 "
                        "{%0,%1,%2,%3}, {%4,%5,%6,%7}, {%8,%9}, {%0,%1,%2,%3};"
                        : "+f"(c[i][j][0]), "+f"(c[i][j][1]),
                          "+f"(c[i][j][2]), "+f"(c[i][j][3])
                        : "r"(a[i][0]), "r"(a[i][1]), "r"(a[i][2]), "r"(a[i][3]),
                          "r"(b[j][0]), "r"(b[j][1]));
        }
        st ^= 1;
        __syncthreads();
    }

    // epilogue -> fp16 H
    int grp = lane >> 2, tg = lane & 3;
    uint32_t* H = (uint32_t*)g_Hh[r];
    #pragma unroll
    for (int i = 0; i < 4; i++) {
        int row0 = m0 + wm * 64 + i * 16 + grp;
        #pragma unroll
        for (int j = 0; j < 4; j++) {
            int nc2 = (wn * 32 + j * 8 + tg * 2) >> 1;
            __half2 lo = __floats2half2_rn(c[i][j][0], c[i][j][1]);
            __half2 hi = __floats2half2_rn(c[i][j][2], c[i][j][3]);
            if (row0 < NNODES)
                H[(size_t)row0 * 64 + nc2] = *(uint32_t*)&lo;
            if (row0 + 8 < NNODES)
                H[(size_t)(row0 + 8) * 64 + nc2] = *(uint32_t*)&hi;
        }
    }
}

// ---------------------------------------------------------------------------
// Scatter: out[n] = sum_r sum_e v * H_r[src]   (fp16 gather, fp32 accumulate)
// ---------------------------------------------------------------------------
__global__ void __launch_bounds__(256) k_scatter(float* __restrict__ out) {
    int n = blockIdx.x * 8 + (threadIdx.x >> 5);
    int lane = threadIdx.x & 31;
    if (n >= NNODES) return;
    float4 acc = make_float4(0.f, 0.f, 0.f, 0.f);
    #pragma unroll
    for (int r = 0; r < NREL; r++) {
        int idx = r * NNODES + n;
        int j0 = g_off[idx], j1 = g_off[idx + 1];
        const uint2* H2 = (const uint2*)g_Hh[r];
        int j = j0;
        for (; j + 1 < j1; j += 2) {
            int   s0 = g_esrc[j],  s1 = g_esrc[j + 1];
            float v0 = g_eval[j],  v1 = g_eval[j + 1];
            uint2 p0 = H2[(size_t)s0 * 32 + lane];
            uint2 p1 = H2[(size_t)s1 * 32 + lane];
            float2 x0 = __half22float2(*(__half2*)&p0.x);
            float2 y0 = __half22float2(*(__half2*)&p0.y);
            float2 x1 = __half22float2(*(__half2*)&p1.x);
            float2 y1 = __half22float2(*(__half2*)&p1.y);
            acc.x += v0 * x0.x + v1 * x1.x;
            acc.y += v0 * x0.y + v1 * x1.y;
            acc.z += v0 * y0.x + v1 * y1.x;
            acc.w += v0 * y0.y + v1 * y1.y;
        }
        if (j < j1) {
            int   s = g_esrc[j];
            float v = g_eval[j];
            uint2 p = H2[(size_t)s * 32 + lane];
            float2 x = __half22float2(*(__half2*)&p.x);
            float2 y = __half22float2(*(__half2*)&p.y);
            acc.x += v * x.x; acc.y += v * x.y;
            acc.z += v * y.x; acc.w += v * y.y;
        }
    }
    ((float4*)out)[(size_t)n * 32 + lane] = acc;
}

// ---------------------------------------------------------------------------
// Streams/events (host objects, created pre-main)
// ---------------------------------------------------------------------------
static cudaStream_t s2 = nullptr;
static cudaEvent_t  evFork, evFill;
static bool g_ok = false;

namespace {
struct StreamInit {
    StreamInit() {
        if (cudaStreamCreateWithFlags(&s2, cudaStreamNonBlocking) != cudaSuccess) return;
        if (cudaEventCreateWithFlags(&evFork, cudaEventDisableTiming) != cudaSuccess) return;
        if (cudaEventCreateWithFlags(&evFill, cudaEventDisableTiming) != cudaSuccess) return;
        g_ok = true;
    }
};
static StreamInit g_si;
}

extern "C" void kernel_launch(void* const* d_in, const int* in_sizes, int n_in,
                              void* d_out, int out_size) {
    const float* inp  = (const float*)d_in[0];
    const int*   src  = (const int*)  d_in[1];
    const int*   dst  = (const int*)  d_in[2];
    const float* vals = (const float*)d_in[3];
    const float* W    = (const float*)d_in[4];
    float* out = (float*)d_out;

    const int SCAN_BLKS = (NIDX + 4095) / 4096;   // 98
    const int PREP_BLKS = (INPSZ / 2 + 255) / 256;
    dim3 ggrid((NNODES + 127) / 128, NREL);       // 391 x 8
    int  sgrid = (NNODES + 7) / 8;

    if (g_ok) {
        cudaEventRecord(evFork, 0);
        cudaStreamWaitEvent(s2, evFork, 0);

        // launch order puts k_gemm at kernel index 3 (ncu profiles index 3)
        k_prep<<<PREP_BLKS, 256>>>((const float2*)inp, (const float2*)W);   // 0
        k_zero<<<(NIDX + 255) / 256, 256, 0, s2>>>();                        // 1
        k_hist<<<(RE + 255) / 256, 256, 0, s2>>>(dst);                       // 2
        k_gemm<<<ggrid, 256>>>();                                            // 3
        k_scanA<<<SCAN_BLKS, 1024, 0, s2>>>();                               // 4
        k_scanB<<<1, 128, 0, s2>>>(SCAN_BLKS);                               // 5
        k_scanC<<<SCAN_BLKS, 1024, 0, s2>>>();                               // 6
        k_fill <<<(RE + 255) / 256, 256, 0, s2>>>(dst, src, vals);           // 7
        cudaEventRecord(evFill, s2);
        cudaStreamWaitEvent(0, evFill, 0);
        k_scatter<<<sgrid, 256>>>(out);                                      // 8
    } else {
        k_prep<<<PREP_BLKS, 256>>>((const float2*)inp, (const float2*)W);
        k_zero<<<(NIDX + 255) / 256, 256>>>();
        k_hist<<<(RE + 255) / 256, 256>>>(dst);
        k_gemm<<<ggrid, 256>>>();
        k_scanA<<<SCAN_BLKS, 1024>>>();
        k_scanB<<<1, 128>>>(SCAN_BLKS);
        k_scanC<<<SCAN_BLKS, 1024>>>();
        k_fill <<<(RE + 255) / 256, 256>>>(dst, src, vals);
        k_scatter<<<sgrid, 256>>>(out);
    }
}

// round 7
// speedup vs baseline: 3.3208x; 1.0904x over previous
#include <cuda_runtime.h>
#include <cuda_fp16.h>
#include <cstdint>

#define NNODES 50000
#define NREL   8
#define NEDGES 100000
#define NIDX   (NREL * NNODES)          // 400000
#define RE     (NREL * NEDGES)          // 800000
#define INPSZ  (NNODES * 128)
#define WSZ    (NREL * 128 * 128)

// ---------------------------------------------------------------------------
// Device scratch
// ---------------------------------------------------------------------------
__device__ __half g_inph[(size_t)INPSZ];              // fp16 inp (12.8 MB)
__device__ __half g_Wh[WSZ];                          // fp16 W
__device__ __half g_Hh[NREL][(size_t)NNODES * 128];   // fp16 H (102.4 MB)
__device__ int    g_cnt[NIDX];
__device__ int    g_cur[NIDX];
__device__ int    g_off[NIDX + 1];
__device__ int    g_bsum[128];
__device__ int    g_bbase[128];
__device__ int    g_esrc[RE];
__device__ float  g_eval[RE];

__device__ __forceinline__ uint32_t smem_u32(const void* p) {
    uint32_t a;
    asm("{ .reg .u64 t; cvta.to.shared.u64 t, %1; cvt.u32.u64 %0, t; }" : "=r"(a) : "l"(p));
    return a;
}
__device__ __forceinline__ void cp16(uint32_t dst, const void* src, uint32_t bytes) {
    asm volatile("cp.async.cg.shared.global [%0], [%1], 16, %2;"
                 :: "r"(dst), "l"(src), "r"(bytes) : "memory");
}

// ---------------------------------------------------------------------------
// Prep: fp32 -> fp16
// ---------------------------------------------------------------------------
__global__ void k_prep(const float2* __restrict__ inp, const float2* __restrict__ W) {
    int i = blockIdx.x * 256 + threadIdx.x;
    if (i < INPSZ / 2) {
        float2 v = inp[i];
        ((__half2*)g_inph)[i] = __floats2half2_rn(v.x, v.y);
    }
    if (i < WSZ / 2) {
        float2 w = W[i];
        ((__half2*)g_Wh)[i] = __floats2half2_rn(w.x, w.y);
    }
}

// ---------------------------------------------------------------------------
// CSR build (side stream)
// ---------------------------------------------------------------------------
__global__ void k_zero() {
    int i = blockIdx.x * 256 + threadIdx.x;
    if (i < NIDX) { g_cnt[i] = 0; g_cur[i] = 0; }
}
__global__ void k_hist(const int* __restrict__ dst) {
    int tid = blockIdx.x * 256 + threadIdx.x;
    if (tid >= RE) return;
    int r = tid / NEDGES;
    atomicAdd(&g_cnt[r * NNODES + dst[tid]], 1);
}
__device__ __forceinline__ int wscan(int x, int lane) {
    #pragma unroll
    for (int o = 1; o < 32; o <<= 1) {
        int y = __shfl_up_sync(0xffffffffu, x, o);
        if (lane >= o) x += y;
    }
    return x;
}
__global__ void k_scanA() {
    __shared__ int ws[32];
    int t = threadIdx.x, lane = t & 31, wid = t >> 5;
    int base = blockIdx.x * 4096 + t * 4;
    int v[4];
    #pragma unroll
    for (int i = 0; i < 4; i++) v[i] = (base + i < NIDX) ? g_cnt[base + i] : 0;
    v[1] += v[0]; v[2] += v[1]; v[3] += v[2];
    int x = wscan(v[3], lane);
    if (lane == 31) ws[wid] = x;
    __syncthreads();
    if (wid == 0) ws[lane] = wscan(ws[lane], lane);
    __syncthreads();
    int pre = (wid ? ws[wid - 1] : 0) + (x - v[3]);
    #pragma unroll
    for (int i = 0; i < 4; i++)
        if (base + i < NIDX) g_off[base + i + 1] = pre + v[i];
    if (t == 1023) g_bsum[blockIdx.x] = ws[31];
}
__global__ void k_scanB(int nblk) {
    __shared__ int ws[4];
    int t = threadIdx.x, lane = t & 31, wid = t >> 5;
    int v = (t < nblk) ? g_bsum[t] : 0;
    int x = wscan(v, lane);
    if (lane == 31) ws[wid] = x;
    __syncthreads();
    if (t == 0) { int a = 0; for (int i = 0; i < 4; i++) { int tmp = ws[i]; ws[i] = a; a += tmp; } }
    __syncthreads();
    int incl = x + ws[wid];
    if (t < nblk) g_bbase[t] = incl - v;
}
__global__ void k_scanC() {
    int t = threadIdx.x;
    int add = g_bbase[blockIdx.x];
    int base = blockIdx.x * 4096 + t * 4;
    #pragma unroll
    for (int i = 0; i < 4; i++)
        if (base + i < NIDX) g_off[base + i + 1] += add;
    if (blockIdx.x == 0 && t == 0) g_off[0] = 0;
}
__global__ void k_fill(const int* __restrict__ dst, const int* __restrict__ src,
                       const float* __restrict__ vals) {
    int tid = blockIdx.x * 256 + threadIdx.x;
    if (tid >= RE) return;
    int r = tid / NEDGES;
    int idx = r * NNODES + dst[tid];
    int p = atomicAdd(&g_cur[idx], 1);
    int pos = g_off[idx] + p;
    g_esrc[pos] = src[tid];
    g_eval[pos] = vals[tid];
}

// ---------------------------------------------------------------------------
// GEMM: H[r] = inp_h @ W_r, 2 relations per CTA, full-K resident tiles.
// dyn smem 96KB: A[128][128]h @0, B0 @32768, B1 @65536 (all XOR-swizzled 16B cols)
// 8 warps (2M x 4N), warp tile 64x32. No syncs inside compute.
// ---------------------------------------------------------------------------
__global__ void __launch_bounds__(256, 2) k_gemm() {
    extern __shared__ __align__(16) char dsm[];
    uint32_t sb = smem_u32(dsm);
    uint32_t ab = sb, bb[2] = { sb + 32768u, sb + 65536u };

    int tid = threadIdx.x;
    int lane = tid & 31, wid = tid >> 5;
    int wm = wid & 1, wn = wid >> 1;
    int m0 = blockIdx.x * 128;
    int rbase = blockIdx.y * 2;

    // ---- prologue: async-load full A, B0, B1 (3 commit groups) ----
    const __half* A = g_inph;
    #pragma unroll
    for (int it = 0; it < 8; it++) {
        int id = it * 256 + tid;            // 2048 16B-chunks
        int row = id >> 4, c = id & 15;
        int grow = m0 + row;
        uint32_t bytes = (grow < NNODES) ? 16u : 0u;
        const __half* src = A + (size_t)(grow < NNODES ? grow : 0) * 128 + c * 8;
        cp16(ab + row * 256 + ((c ^ (row & 7)) * 16), src, bytes);
    }
    asm volatile("cp.async.commit_group;" ::: "memory");
    #pragma unroll
    for (int rr = 0; rr < 2; rr++) {
        const __half* B = g_Wh + (rbase + rr) * 16384;
        #pragma unroll
        for (int it = 0; it < 8; it++) {
            int id = it * 256 + tid;
            int row = id >> 4, c = id & 15;
            cp16(bb[rr] + row * 256 + ((c ^ (row & 7)) * 16), B + row * 128 + c * 8, 16u);
        }
        asm volatile("cp.async.commit_group;" ::: "memory");
    }

    // per-lane ldmatrix address pieces
    uint32_t arow = (uint32_t)(wm * 64 + (lane & 15));
    uint32_t axor = arow & 7;
    uint32_t alh  = (uint32_t)(lane >> 4);
    uint32_t abase_l = ab + arow * 256;
    uint32_t brow_l  = (uint32_t)(lane & 15);
    uint32_t bxor    = (uint32_t)(lane & 7);

    asm volatile("cp.async.wait_group 1;" ::: "memory");   // A + B0 ready
    __syncthreads();

    #pragma unroll
    for (int rr = 0; rr < 2; rr++) {
        if (rr == 1) {
            asm volatile("cp.async.wait_group 0;" ::: "memory");
            __syncthreads();
        }
        uint32_t bsb = bb[rr];

        float c[4][4][4];
        #pragma unroll
        for (int i = 0; i < 4; i++)
            #pragma unroll
            for (int j = 0; j < 4; j++)
                c[i][j][0] = c[i][j][1] = c[i][j][2] = c[i][j][3] = 0.f;

        #pragma unroll
        for (int kb = 0; kb < 4; kb++) {
            #pragma unroll
            for (int kk = 0; kk < 2; kk++) {
                uint32_t a[4][4], b[4][2];
                uint32_t ach = (uint32_t)(kb * 4 + kk * 2) + alh;
                #pragma unroll
                for (int i = 0; i < 4; i++) {
                    uint32_t ad = abase_l + (uint32_t)(i * 16 * 256) +
                                  ((ach ^ axor) * 16);
                    asm volatile("ldmatrix.sync.aligned.m8n8.x4.shared.b16 "
                                 "{%0,%1,%2,%3}, [%4];"
                                 : "=r"(a[i][0]), "=r"(a[i][1]),
                                   "=r"(a[i][2]), "=r"(a[i][3])
                                 : "r"(ad));
                }
                uint32_t brow = (uint32_t)(kb * 32 + kk * 16) + brow_l;
                #pragma unroll
                for (int p = 0; p < 2; p++) {
                    uint32_t nch = (uint32_t)(wn * 4 + p * 2) + alh;
                    uint32_t bd = bsb + brow * 256 + ((nch ^ bxor) * 16);
                    asm volatile("ldmatrix.sync.aligned.m8n8.x4.trans.shared.b16 "
                                 "{%0,%1,%2,%3}, [%4];"
                                 : "=r"(b[p*2][0]), "=r"(b[p*2][1]),
                                   "=r"(b[p*2+1][0]), "=r"(b[p*2+1][1])
                                 : "r"(bd));
                }
                #pragma unroll
                for (int i = 0; i < 4; i++)
                    #pragma unroll
                    for (int j = 0; j < 4; j++)
                        asm volatile(
                            "mma.sync.aligned.m16n8k16.row.col.f32.f16.f16.f32 "
                            "{%0,%1,%2,%3}, {%4,%5,%6,%7}, {%8,%9}, {%0,%1,%2,%3};"
                            : "+f"(c[i][j][0]), "+f"(c[i][j][1]),
                              "+f"(c[i][j][2]), "+f"(c[i][j][3])
                            : "r"(a[i][0]), "r"(a[i][1]), "r"(a[i][2]), "r"(a[i][3]),
                              "r"(b[j][0]), "r"(b[j][1]));
            }
        }

        // epilogue -> fp16 H[rbase+rr]
        int grp = lane >> 2, tg = lane & 3;
        uint32_t* H = (uint32_t*)g_Hh[rbase + rr];
        #pragma unroll
        for (int i = 0; i < 4; i++) {
            int row0 = m0 + wm * 64 + i * 16 + grp;
            #pragma unroll
            for (int j = 0; j < 4; j++) {
                int nc2 = (wn * 32 + j * 8 + tg * 2) >> 1;
                __half2 lo = __floats2half2_rn(c[i][j][0], c[i][j][1]);
                __half2 hi = __floats2half2_rn(c[i][j][2], c[i][j][3]);
                if (row0 < NNODES)
                    H[(size_t)row0 * 64 + nc2] = *(uint32_t*)&lo;
                if (row0 + 8 < NNODES)
                    H[(size_t)(row0 + 8) * 64 + nc2] = *(uint32_t*)&hi;
            }
        }
    }
}

// ---------------------------------------------------------------------------
// Scatter: out[n] = sum_r sum_e v * H_r[src]; all 8 segment bounds preloaded
// ---------------------------------------------------------------------------
__global__ void __launch_bounds__(256) k_scatter(float* __restrict__ out) {
    int n = blockIdx.x * 8 + (threadIdx.x >> 5);
    int lane = threadIdx.x & 31;
    if (n >= NNODES) return;

    int j0[NREL], j1[NREL];
    #pragma unroll
    for (int r = 0; r < NREL; r++) {
        int idx = r * NNODES + n;
        j0[r] = __ldg(&g_off[idx]);
        j1[r] = __ldg(&g_off[idx + 1]);
    }

    float4 acc = make_float4(0.f, 0.f, 0.f, 0.f);
    #pragma unroll
    for (int r = 0; r < NREL; r++) {
        const uint2* H2 = (const uint2*)g_Hh[r];
        int j = j0[r], e = j1[r];
        for (; j + 1 < e; j += 2) {
            int   s0 = __ldg(&g_esrc[j]),  s1 = __ldg(&g_esrc[j + 1]);
            float v0 = __ldg(&g_eval[j]),  v1 = __ldg(&g_eval[j + 1]);
            uint2 p0 = __ldg(&H2[(size_t)s0 * 32 + lane]);
            uint2 p1 = __ldg(&H2[(size_t)s1 * 32 + lane]);
            float2 x0 = __half22float2(*(__half2*)&p0.x);
            float2 y0 = __half22float2(*(__half2*)&p0.y);
            float2 x1 = __half22float2(*(__half2*)&p1.x);
            float2 y1 = __half22float2(*(__half2*)&p1.y);
            acc.x += v0 * x0.x + v1 * x1.x;
            acc.y += v0 * x0.y + v1 * x1.y;
            acc.z += v0 * y0.x + v1 * y1.x;
            acc.w += v0 * y0.y + v1 * y1.y;
        }
        if (j < e) {
            int   s = __ldg(&g_esrc[j]);
            float v = __ldg(&g_eval[j]);
            uint2 p = __ldg(&H2[(size_t)s * 32 + lane]);
            float2 x = __half22float2(*(__half2*)&p.x);
            float2 y = __half22float2(*(__half2*)&p.y);
            acc.x += v * x.x; acc.y += v * x.y;
            acc.z += v * y.x; acc.w += v * y.y;
        }
    }
    ((float4*)out)[(size_t)n * 32 + lane] = acc;
}

// ---------------------------------------------------------------------------
// Streams/events + smem opt-in (host objects, pre-main)
// ---------------------------------------------------------------------------
static cudaStream_t s2 = nullptr;
static cudaEvent_t  evFork, evFill;
static bool g_ok = false;

#define GEMM_SMEM 98304

namespace {
struct StreamInit {
    StreamInit() {
        cudaFuncSetAttribute((const void*)k_gemm,
                             cudaFuncAttributeMaxDynamicSharedMemorySize, GEMM_SMEM);
        if (cudaStreamCreateWithFlags(&s2, cudaStreamNonBlocking) != cudaSuccess) return;
        if (cudaEventCreateWithFlags(&evFork, cudaEventDisableTiming) != cudaSuccess) return;
        if (cudaEventCreateWithFlags(&evFill, cudaEventDisableTiming) != cudaSuccess) return;
        g_ok = true;
    }
};
static StreamInit g_si;
}

extern "C" void kernel_launch(void* const* d_in, const int* in_sizes, int n_in,
                              void* d_out, int out_size) {
    const float* inp  = (const float*)d_in[0];
    const int*   src  = (const int*)  d_in[1];
    const int*   dst  = (const int*)  d_in[2];
    const float* vals = (const float*)d_in[3];
    const float* W    = (const float*)d_in[4];
    float* out = (float*)d_out;

    // idempotent (capture-safe, not a stream op)
    cudaFuncSetAttribute((const void*)k_gemm,
                         cudaFuncAttributeMaxDynamicSharedMemorySize, GEMM_SMEM);

    const int SCAN_BLKS = (NIDX + 4095) / 4096;   // 98
    const int PREP_BLKS = (INPSZ / 2 + 255) / 256;
    dim3 ggrid((NNODES + 127) / 128, 4);          // 391 x 4 (2 rel/CTA)
    int  sgrid = (NNODES + 7) / 8;

    if (g_ok) {
        cudaEventRecord(evFork, 0);
        cudaStreamWaitEvent(s2, evFork, 0);

        // k_gemm stays at kernel index 3 for ncu
        k_prep<<<PREP_BLKS, 256>>>((const float2*)inp, (const float2*)W);   // 0
        k_zero<<<(NIDX + 255) / 256, 256, 0, s2>>>();                        // 1
        k_hist<<<(RE + 255) / 256, 256, 0, s2>>>(dst);                       // 2
        k_gemm<<<ggrid, 256, GEMM_SMEM>>>();                                 // 3
        k_scanA<<<SCAN_BLKS, 1024, 0, s2>>>();                               // 4
        k_scanB<<<1, 128, 0, s2>>>(SCAN_BLKS);                               // 5
        k_scanC<<<SCAN_BLKS, 1024, 0, s2>>>();                               // 6
        k_fill <<<(RE + 255) / 256, 256, 0, s2>>>(dst, src, vals);           // 7
        cudaEventRecord(evFill, s2);
        cudaStreamWaitEvent(0, evFill, 0);
        k_scatter<<<sgrid, 256>>>(out);                                      // 8
    } else {
        k_prep<<<PREP_BLKS, 256>>>((const float2*)inp, (const float2*)W);
        k_zero<<<(NIDX + 255) / 256, 256>>>();
        k_hist<<<(RE + 255) / 256, 256>>>(dst);
        k_gemm<<<ggrid, 256, GEMM_SMEM>>>();
        k_scanA<<<SCAN_BLKS, 1024>>>();
        k_scanB<<<1, 128>>>(SCAN_BLKS);
        k_scanC<<<SCAN_BLKS, 1024>>>();
        k_fill <<<(RE + 255) / 256, 256>>>(dst, src, vals);
        k_scatter<<<sgrid, 256>>>(out);
    }
}

// round 8
// speedup vs baseline: 3.4548x; 1.0404x over previous
#include <cuda_runtime.h>
#include <cuda_fp16.h>
#include <cstdint>

#define NNODES 50000
#define NREL   8
#define NEDGES 100000
#define NIDX   (NREL * NNODES)          // 400000
#define RE     (NREL * NEDGES)          // 800000
#define INPSZ  (NNODES * 128)
#define WSZ    (NREL * 128 * 128)

// ---------------------------------------------------------------------------
// Device scratch
// ---------------------------------------------------------------------------
__device__ __half g_inph[(size_t)INPSZ];              // fp16 inp (12.8 MB)
__device__ __half g_Wh[WSZ];                          // fp16 W
__device__ __half g_Hh[NREL][(size_t)NNODES * 128];   // fp16 H (102.4 MB)
__device__ int    g_cnt[NIDX];
__device__ int    g_cur[NIDX];
__device__ int    g_off[NIDX + 1];
__device__ int    g_bsum[128];
__device__ int    g_bbase[128];
__device__ int    g_esrc[RE];
__device__ float  g_eval[RE];

__device__ __forceinline__ uint32_t smem_u32(const void* p) {
    uint32_t a;
    asm("{ .reg .u64 t; cvta.to.shared.u64 t, %1; cvt.u32.u64 %0, t; }" : "=r"(a) : "l"(p));
    return a;
}
__device__ __forceinline__ void cp16(uint32_t dst, const void* src, uint32_t bytes) {
    asm volatile("cp.async.cg.shared.global [%0], [%1], 16, %2;"
                 :: "r"(dst), "l"(src), "r"(bytes) : "memory");
}

// ---------------------------------------------------------------------------
// Prep: fp32 -> fp16
// ---------------------------------------------------------------------------
__global__ void k_prep(const float2* __restrict__ inp, const float2* __restrict__ W) {
    int i = blockIdx.x * 256 + threadIdx.x;
    if (i < INPSZ / 2) {
        float2 v = inp[i];
        ((__half2*)g_inph)[i] = __floats2half2_rn(v.x, v.y);
    }
    if (i < WSZ / 2) {
        float2 w = W[i];
        ((__half2*)g_Wh)[i] = __floats2half2_rn(w.x, w.y);
    }
}

// ---------------------------------------------------------------------------
// CSR build (side stream)
// ---------------------------------------------------------------------------
__global__ void k_zero() {
    int i = blockIdx.x * 256 + threadIdx.x;
    if (i < NIDX) { g_cnt[i] = 0; g_cur[i] = 0; }
}
__global__ void k_hist(const int* __restrict__ dst) {
    int tid = blockIdx.x * 256 + threadIdx.x;
    if (tid >= RE) return;
    int r = tid / NEDGES;
    atomicAdd(&g_cnt[r * NNODES + dst[tid]], 1);
}
__device__ __forceinline__ int wscan(int x, int lane) {
    #pragma unroll
    for (int o = 1; o < 32; o <<= 1) {
        int y = __shfl_up_sync(0xffffffffu, x, o);
        if (lane >= o) x += y;
    }
    return x;
}
__global__ void k_scanA() {
    __shared__ int ws[32];
    int t = threadIdx.x, lane = t & 31, wid = t >> 5;
    int base = blockIdx.x * 4096 + t * 4;
    int v[4];
    #pragma unroll
    for (int i = 0; i < 4; i++) v[i] = (base + i < NIDX) ? g_cnt[base + i] : 0;
    v[1] += v[0]; v[2] += v[1]; v[3] += v[2];
    int x = wscan(v[3], lane);
    if (lane == 31) ws[wid] = x;
    __syncthreads();
    if (wid == 0) ws[lane] = wscan(ws[lane], lane);
    __syncthreads();
    int pre = (wid ? ws[wid - 1] : 0) + (x - v[3]);
    #pragma unroll
    for (int i = 0; i < 4; i++)
        if (base + i < NIDX) g_off[base + i + 1] = pre + v[i];
    if (t == 1023) g_bsum[blockIdx.x] = ws[31];
}
__global__ void k_scanB(int nblk) {
    __shared__ int ws[4];
    int t = threadIdx.x, lane = t & 31, wid = t >> 5;
    int v = (t < nblk) ? g_bsum[t] : 0;
    int x = wscan(v, lane);
    if (lane == 31) ws[wid] = x;
    __syncthreads();
    if (t == 0) { int a = 0; for (int i = 0; i < 4; i++) { int tmp = ws[i]; ws[i] = a; a += tmp; } }
    __syncthreads();
    int incl = x + ws[wid];
    if (t < nblk) g_bbase[t] = incl - v;
}
__global__ void k_scanC() {
    int t = threadIdx.x;
    int add = g_bbase[blockIdx.x];
    int base = blockIdx.x * 4096 + t * 4;
    #pragma unroll
    for (int i = 0; i < 4; i++)
        if (base + i < NIDX) g_off[base + i + 1] += add;
    if (blockIdx.x == 0 && t == 0) g_off[0] = 0;
}
__global__ void k_fill(const int* __restrict__ dst, const int* __restrict__ src,
                       const float* __restrict__ vals) {
    int tid = blockIdx.x * 256 + threadIdx.x;
    if (tid >= RE) return;
    int r = tid / NEDGES;
    int idx = r * NNODES + dst[tid];
    int p = atomicAdd(&g_cur[idx], 1);
    int pos = g_off[idx] + p;
    g_esrc[pos] = src[tid];
    g_eval[pos] = vals[tid];
}

// ---------------------------------------------------------------------------
// GEMM: H[r] = inp_h @ W_r for 4 relations (half), 2 rel/CTA, full-K resident.
// dyn smem 96KB: A @0, B0 @32768, B1 @65536 (XOR-swizzled 16B cols)
// ---------------------------------------------------------------------------
__global__ void __launch_bounds__(256, 2) k_gemm(int half) {
    extern __shared__ __align__(16) char dsm[];
    uint32_t sb = smem_u32(dsm);
    uint32_t ab = sb, bb[2] = { sb + 32768u, sb + 65536u };

    int tid = threadIdx.x;
    int lane = tid & 31, wid = tid >> 5;
    int wm = wid & 1, wn = wid >> 1;
    int m0 = blockIdx.x * 128;
    int rbase = half * 4 + blockIdx.y * 2;

    const __half* A = g_inph;
    #pragma unroll
    for (int it = 0; it < 8; it++) {
        int id = it * 256 + tid;
        int row = id >> 4, c = id & 15;
        int grow = m0 + row;
        uint32_t bytes = (grow < NNODES) ? 16u : 0u;
        const __half* src = A + (size_t)(grow < NNODES ? grow : 0) * 128 + c * 8;
        cp16(ab + row * 256 + ((c ^ (row & 7)) * 16), src, bytes);
    }
    asm volatile("cp.async.commit_group;" ::: "memory");
    #pragma unroll
    for (int rr = 0; rr < 2; rr++) {
        const __half* B = g_Wh + (rbase + rr) * 16384;
        #pragma unroll
        for (int it = 0; it < 8; it++) {
            int id = it * 256 + tid;
            int row = id >> 4, c = id & 15;
            cp16(bb[rr] + row * 256 + ((c ^ (row & 7)) * 16), B + row * 128 + c * 8, 16u);
        }
        asm volatile("cp.async.commit_group;" ::: "memory");
    }

    uint32_t arow = (uint32_t)(wm * 64 + (lane & 15));
    uint32_t axor = arow & 7;
    uint32_t alh  = (uint32_t)(lane >> 4);
    uint32_t abase_l = ab + arow * 256;
    uint32_t brow_l  = (uint32_t)(lane & 15);
    uint32_t bxor    = (uint32_t)(lane & 7);

    asm volatile("cp.async.wait_group 1;" ::: "memory");
    __syncthreads();

    #pragma unroll
    for (int rr = 0; rr < 2; rr++) {
        if (rr == 1) {
            asm volatile("cp.async.wait_group 0;" ::: "memory");
            __syncthreads();
        }
        uint32_t bsb = bb[rr];

        float c[4][4][4];
        #pragma unroll
        for (int i = 0; i < 4; i++)
            #pragma unroll
            for (int j = 0; j < 4; j++)
                c[i][j][0] = c[i][j][1] = c[i][j][2] = c[i][j][3] = 0.f;

        #pragma unroll
        for (int kb = 0; kb < 4; kb++) {
            #pragma unroll
            for (int kk = 0; kk < 2; kk++) {
                uint32_t a[4][4], b[4][2];
                uint32_t ach = (uint32_t)(kb * 4 + kk * 2) + alh;
                #pragma unroll
                for (int i = 0; i < 4; i++) {
                    uint32_t ad = abase_l + (uint32_t)(i * 16 * 256) +
                                  ((ach ^ axor) * 16);
                    asm volatile("ldmatrix.sync.aligned.m8n8.x4.shared.b16 "
                                 "{%0,%1,%2,%3}, [%4];"
                                 : "=r"(a[i][0]), "=r"(a[i][1]),
                                   "=r"(a[i][2]), "=r"(a[i][3])
                                 : "r"(ad));
                }
                uint32_t brow = (uint32_t)(kb * 32 + kk * 16) + brow_l;
                #pragma unroll
                for (int p = 0; p < 2; p++) {
                    uint32_t nch = (uint32_t)(wn * 4 + p * 2) + alh;
                    uint32_t bd = bsb + brow * 256 + ((nch ^ bxor) * 16);
                    asm volatile("ldmatrix.sync.aligned.m8n8.x4.trans.shared.b16 "
                                 "{%0,%1,%2,%3}, [%4];"
                                 : "=r"(b[p*2][0]), "=r"(b[p*2][1]),
                                   "=r"(b[p*2+1][0]), "=r"(b[p*2+1][1])
                                 : "r"(bd));
                }
                #pragma unroll
                for (int i = 0; i < 4; i++)
                    #pragma unroll
                    for (int j = 0; j < 4; j++)
                        asm volatile(
                            "mma.sync.aligned.m16n8k16.row.col.f32.f16.f16.f32 "
                            "{%0,%1,%2,%3}, {%4,%5,%6,%7}, {%8,%9}, {%0,%1,%2,%3};"
                            : "+f"(c[i][j][0]), "+f"(c[i][j][1]),
                              "+f"(c[i][j][2]), "+f"(c[i][j][3])
                            : "r"(a[i][0]), "r"(a[i][1]), "r"(a[i][2]), "r"(a[i][3]),
                              "r"(b[j][0]), "r"(b[j][1]));
            }
        }

        int grp = lane >> 2, tg = lane & 3;
        uint32_t* H = (uint32_t*)g_Hh[rbase + rr];
        #pragma unroll
        for (int i = 0; i < 4; i++) {
            int row0 = m0 + wm * 64 + i * 16 + grp;
            #pragma unroll
            for (int j = 0; j < 4; j++) {
                int nc2 = (wn * 32 + j * 8 + tg * 2) >> 1;
                __half2 lo = __floats2half2_rn(c[i][j][0], c[i][j][1]);
                __half2 hi = __floats2half2_rn(c[i][j][2], c[i][j][3]);
                if (row0 < NNODES)
                    H[(size_t)row0 * 64 + nc2] = *(uint32_t*)&lo;
                if (row0 + 8 < NNODES)
                    H[(size_t)(row0 + 8) * 64 + nc2] = *(uint32_t*)&hi;
            }
        }
    }
}

// ---------------------------------------------------------------------------
// Scatter (half): out[n] (+)= sum over 4 relations of sum_e v * H_r[src]
// ---------------------------------------------------------------------------
__global__ void __launch_bounds__(256) k_scatter(int half, float* __restrict__ out) {
    int n = blockIdx.x * 8 + (threadIdx.x >> 5);
    int lane = threadIdx.x & 31;
    if (n >= NNODES) return;

    int rb = half * 4;
    int j0[4], j1[4];
    #pragma unroll
    for (int q = 0; q < 4; q++) {
        int idx = (rb + q) * NNODES + n;
        j0[q] = __ldg(&g_off[idx]);
        j1[q] = __ldg(&g_off[idx + 1]);
    }

    float4 acc;
    if (half == 0) acc = make_float4(0.f, 0.f, 0.f, 0.f);
    else           acc = ((float4*)out)[(size_t)n * 32 + lane];

    #pragma unroll
    for (int q = 0; q < 4; q++) {
        const uint2* H2 = (const uint2*)g_Hh[rb + q];
        int j = j0[q], e = j1[q];
        for (; j + 1 < e; j += 2) {
            int   s0 = __ldg(&g_esrc[j]),  s1 = __ldg(&g_esrc[j + 1]);
            float v0 = __ldg(&g_eval[j]),  v1 = __ldg(&g_eval[j + 1]);
            uint2 p0 = __ldg(&H2[(size_t)s0 * 32 + lane]);
            uint2 p1 = __ldg(&H2[(size_t)s1 * 32 + lane]);
            float2 x0 = __half22float2(*(__half2*)&p0.x);
            float2 y0 = __half22float2(*(__half2*)&p0.y);
            float2 x1 = __half22float2(*(__half2*)&p1.x);
            float2 y1 = __half22float2(*(__half2*)&p1.y);
            acc.x += v0 * x0.x + v1 * x1.x;
            acc.y += v0 * x0.y + v1 * x1.y;
            acc.z += v0 * y0.x + v1 * y1.x;
            acc.w += v0 * y0.y + v1 * y1.y;
        }
        if (j < e) {
            int   s = __ldg(&g_esrc[j]);
            float v = __ldg(&g_eval[j]);
            uint2 p = __ldg(&H2[(size_t)s * 32 + lane]);
            float2 x = __half22float2(*(__half2*)&p.x);
            float2 y = __half22float2(*(__half2*)&p.y);
            acc.x += v * x.x; acc.y += v * x.y;
            acc.z += v * y.x; acc.w += v * y.y;
        }
    }
    ((float4*)out)[(size_t)n * 32 + lane] = acc;
}

// ---------------------------------------------------------------------------
// Streams/events + smem opt-in (host objects, pre-main)
// ---------------------------------------------------------------------------
static cudaStream_t s2 = nullptr;
static cudaEvent_t  evFork, evG0, evS0;
static bool g_ok = false;

#define GEMM_SMEM 98304

namespace {
struct StreamInit {
    StreamInit() {
        cudaFuncSetAttribute((const void*)k_gemm,
                             cudaFuncAttributeMaxDynamicSharedMemorySize, GEMM_SMEM);
        if (cudaStreamCreateWithFlags(&s2, cudaStreamNonBlocking) != cudaSuccess) return;
        if (cudaEventCreateWithFlags(&evFork, cudaEventDisableTiming) != cudaSuccess) return;
        if (cudaEventCreateWithFlags(&evG0,   cudaEventDisableTiming) != cudaSuccess) return;
        if (cudaEventCreateWithFlags(&evS0,   cudaEventDisableTiming) != cudaSuccess) return;
        g_ok = true;
    }
};
static StreamInit g_si;
}

extern "C" void kernel_launch(void* const* d_in, const int* in_sizes, int n_in,
                              void* d_out, int out_size) {
    const float* inp  = (const float*)d_in[0];
    const int*   src  = (const int*)  d_in[1];
    const int*   dst  = (const int*)  d_in[2];
    const float* vals = (const float*)d_in[3];
    const float* W    = (const float*)d_in[4];
    float* out = (float*)d_out;

    cudaFuncSetAttribute((const void*)k_gemm,
                         cudaFuncAttributeMaxDynamicSharedMemorySize, GEMM_SMEM);

    const int SCAN_BLKS = (NIDX + 4095) / 4096;   // 98
    const int PREP_BLKS = (INPSZ / 2 + 255) / 256;
    dim3 ggrid((NNODES + 127) / 128, 2);          // 391 x 2 (4 rel per launch)
    int  sgrid = (NNODES + 7) / 8;

    if (g_ok) {
        cudaEventRecord(evFork, 0);
        cudaStreamWaitEvent(s2, evFork, 0);

        // main: prep -> gemm0 -> gemm1 -> (wait scatter0) -> scatter1
        // s2:   CSR build -> (wait gemm0) -> scatter0
        k_prep<<<PREP_BLKS, 256>>>((const float2*)inp, (const float2*)W);   // 0
        k_zero<<<(NIDX + 255) / 256, 256, 0, s2>>>();                        // 1
        k_hist<<<(RE + 255) / 256, 256, 0, s2>>>(dst);                       // 2
        k_gemm<<<ggrid, 256, GEMM_SMEM>>>(0);                                // 3 (ncu)
        cudaEventRecord(evG0, 0);
        k_scanA<<<SCAN_BLKS, 1024, 0, s2>>>();                               // 4
        k_scanB<<<1, 128, 0, s2>>>(SCAN_BLKS);                               // 5
        k_scanC<<<SCAN_BLKS, 1024, 0, s2>>>();                               // 6
        k_fill <<<(RE + 255) / 256, 256, 0, s2>>>(dst, src, vals);           // 7
        k_gemm<<<ggrid, 256, GEMM_SMEM>>>(1);                                // 8
        cudaStreamWaitEvent(s2, evG0, 0);
        k_scatter<<<sgrid, 256, 0, s2>>>(0, out);                            // 9
        cudaEventRecord(evS0, s2);
        cudaStreamWaitEvent(0, evS0, 0);
        k_scatter<<<sgrid, 256>>>(1, out);                                   // 10
    } else {
        k_prep<<<PREP_BLKS, 256>>>((const float2*)inp, (const float2*)W);
        k_zero<<<(NIDX + 255) / 256, 256>>>();
        k_hist<<<(RE + 255) / 256, 256>>>(dst);
        k_gemm<<<ggrid, 256, GEMM_SMEM>>>(0);
        k_scanA<<<SCAN_BLKS, 1024>>>();
        k_scanB<<<1, 128>>>(SCAN_BLKS);
        k_scanC<<<SCAN_BLKS, 1024>>>();
        k_fill <<<(RE + 255) / 256, 256>>>(dst, src, vals);
        k_gemm<<<ggrid, 256, GEMM_SMEM>>>(1);
        k_scatter<<<sgrid, 256>>>(0, out);
        k_scatter<<<sgrid, 256>>>(1, out);
    }
}